// round 1
// baseline (speedup 1.0000x reference)
#include <cuda_runtime.h>
#include <math.h>

#define N_SEQ 8192
#define HDIM  128
#define BM    64
#define BN    64
#define NTHREADS 256
#define PT_STRIDE 68   // 64 + 4 pad, keeps float4 alignment

// dynamic smem layout (floats):
//   Qt : [HDIM][BM]  swizzled   (8192)
//   Kt : [HDIM][BN]  swizzled   (8192)
//   Vs : [BN][HDIM]  straight   (8192)
//   Pt : [BN][PT_STRIDE]        (4352)
#define SM_QT 0
#define SM_KT (SM_QT + HDIM*BM)
#define SM_VS (SM_KT + HDIM*BN)
#define SM_PT (SM_VS + BN*HDIM)
#define SMEM_FLOATS (SM_PT + BN*PT_STRIDE)
#define SMEM_BYTES (SMEM_FLOATS * 4)

#define LOG2E 1.4426950408889634f

// swizzled float-offset of element (d, j) in a [HDIM][64] d-major tile:
// float4-group j>>2 is XORed with (d>>2)&15 -> conflict-free reads AND
// ~2-way (instead of 32-way) transpose stores.
__device__ __forceinline__ int sw_base(int d, int j4) {
    return d * 64 + (((j4 ^ ((d >> 2) & 15)) << 2));
}

__global__ __launch_bounds__(NTHREADS, 1)
void fa_fp32_kernel(const float* __restrict__ Q,
                    const float* __restrict__ K,
                    const float* __restrict__ V,
                    float* __restrict__ O) {
    extern __shared__ float sm[];
    float* Qt = sm + SM_QT;
    float* Kt = sm + SM_KT;
    float* Vs = sm + SM_VS;
    float* Pt = sm + SM_PT;

    const int tid = threadIdx.x;
    const int tx = tid & 15;      // 0..15 : S cols 4*tx.., O cols 8*tx..
    const int ty = tid >> 4;      // 0..15 : rows 4*ty..
    const int qbase = blockIdx.x * BM;

    // ---- load Q block, transposed + swizzled (one-time) ----
    for (int idx = tid; idx < BM * (HDIM / 4); idx += NTHREADS) {
        int i  = idx >> 5;          // row in block
        int c4 = idx & 31;          // float4 column
        float4 qv = reinterpret_cast<const float4*>(Q + (size_t)(qbase + i) * HDIM)[c4];
        int d0 = c4 * 4;
        int jlow = i & 3, j4 = i >> 2;
        Qt[sw_base(d0 + 0, j4) + jlow] = qv.x;
        Qt[sw_base(d0 + 1, j4) + jlow] = qv.y;
        Qt[sw_base(d0 + 2, j4) + jlow] = qv.z;
        Qt[sw_base(d0 + 3, j4) + jlow] = qv.w;
    }

    float o[4][8];
    float m[4], l[4];
#pragma unroll
    for (int r = 0; r < 4; r++) {
        m[r] = -INFINITY; l[r] = 0.f;
#pragma unroll
        for (int c = 0; c < 8; c++) o[r][c] = 0.f;
    }

    for (int t = 0; t < N_SEQ / BN; t++) {
        __syncthreads();   // previous PV done -> safe to overwrite Kt/Vs

        // ---- load K tile (transposed+swizzled) and V tile (straight) ----
        const float* Kg = K + (size_t)t * BN * HDIM;
        const float* Vg = V + (size_t)t * BN * HDIM;
        for (int idx = tid; idx < BN * (HDIM / 4); idx += NTHREADS) {
            int j  = idx >> 5;
            int c4 = idx & 31;
            float4 kv = reinterpret_cast<const float4*>(Kg)[idx];
            int d0 = c4 * 4;
            int jlow = j & 3, j4 = j >> 2;
            Kt[sw_base(d0 + 0, j4) + jlow] = kv.x;
            Kt[sw_base(d0 + 1, j4) + jlow] = kv.y;
            Kt[sw_base(d0 + 2, j4) + jlow] = kv.z;
            Kt[sw_base(d0 + 3, j4) + jlow] = kv.w;
            reinterpret_cast<float4*>(Vs)[idx] = reinterpret_cast<const float4*>(Vg)[idx];
        }
        __syncthreads();

        // ---- S = Q K^T (per-thread 4x4 tile) ----
        float s[4][4];
#pragma unroll
        for (int r = 0; r < 4; r++)
#pragma unroll
            for (int c = 0; c < 4; c++) s[r][c] = 0.f;

        for (int dd = 0; dd < HDIM; dd += 4) {
            const int swmask = (dd >> 2) & 15;
            const int qoff = ((ty ^ swmask) << 2);
            const int koff = ((tx ^ swmask) << 2);
#pragma unroll
            for (int u = 0; u < 4; u++) {
                const int d = dd + u;
                const float4 qv = *reinterpret_cast<const float4*>(Qt + d * 64 + qoff);
                const float4 kv = *reinterpret_cast<const float4*>(Kt + d * 64 + koff);
                s[0][0] += qv.x * kv.x; s[0][1] += qv.x * kv.y; s[0][2] += qv.x * kv.z; s[0][3] += qv.x * kv.w;
                s[1][0] += qv.y * kv.x; s[1][1] += qv.y * kv.y; s[1][2] += qv.y * kv.z; s[1][3] += qv.y * kv.w;
                s[2][0] += qv.z * kv.x; s[2][1] += qv.z * kv.y; s[2][2] += qv.z * kv.z; s[2][3] += qv.z * kv.w;
                s[3][0] += qv.w * kv.x; s[3][1] += qv.w * kv.y; s[3][2] += qv.w * kv.z; s[3][3] += qv.w * kv.w;
            }
        }

        // ---- online softmax (row groups = 16 lanes sharing ty) ----
        float alpha[4];
#pragma unroll
        for (int r = 0; r < 4; r++) {
            float rm = fmaxf(fmaxf(s[r][0], s[r][1]), fmaxf(s[r][2], s[r][3]));
#pragma unroll
            for (int off = 8; off >= 1; off >>= 1)
                rm = fmaxf(rm, __shfl_xor_sync(0xffffffffu, rm, off));
            const float mn = fmaxf(m[r], rm);
            const float al = exp2f((m[r] - mn) * LOG2E);
            float rs = 0.f;
#pragma unroll
            for (int c = 0; c < 4; c++) {
                const float p = exp2f((s[r][c] - mn) * LOG2E);
                s[r][c] = p;
                rs += p;
            }
#pragma unroll
            for (int off = 8; off >= 1; off >>= 1)
                rs += __shfl_xor_sync(0xffffffffu, rs, off);
            l[r] = l[r] * al + rs;
            m[r] = mn;
            alpha[r] = al;
        }

        // ---- write P transposed: Pt[j][i] ----
#pragma unroll
        for (int c = 0; c < 4; c++) {
#pragma unroll
            for (int r = 0; r < 4; r++)
                Pt[(4 * tx + c) * PT_STRIDE + 4 * ty + r] = s[r][c];
        }
        __syncthreads();

        // ---- O = O*alpha + P @ V ----
#pragma unroll
        for (int r = 0; r < 4; r++)
#pragma unroll
            for (int c = 0; c < 8; c++) o[r][c] *= alpha[r];

#pragma unroll 4
        for (int j = 0; j < BN; j++) {
            const float4 pv = *reinterpret_cast<const float4*>(Pt + j * PT_STRIDE + 4 * ty);
            const float4 va = *reinterpret_cast<const float4*>(Vs + j * HDIM + 8 * tx);
            const float4 vb = *reinterpret_cast<const float4*>(Vs + j * HDIM + 8 * tx + 4);
            o[0][0] += pv.x * va.x; o[0][1] += pv.x * va.y; o[0][2] += pv.x * va.z; o[0][3] += pv.x * va.w;
            o[0][4] += pv.x * vb.x; o[0][5] += pv.x * vb.y; o[0][6] += pv.x * vb.z; o[0][7] += pv.x * vb.w;
            o[1][0] += pv.y * va.x; o[1][1] += pv.y * va.y; o[1][2] += pv.y * va.z; o[1][3] += pv.y * va.w;
            o[1][4] += pv.y * vb.x; o[1][5] += pv.y * vb.y; o[1][6] += pv.y * vb.z; o[1][7] += pv.y * vb.w;
            o[2][0] += pv.z * va.x; o[2][1] += pv.z * va.y; o[2][2] += pv.z * va.z; o[2][3] += pv.z * va.w;
            o[2][4] += pv.z * vb.x; o[2][5] += pv.z * vb.y; o[2][6] += pv.z * vb.z; o[2][7] += pv.z * vb.w;
            o[3][0] += pv.w * va.x; o[3][1] += pv.w * va.y; o[3][2] += pv.w * va.z; o[3][3] += pv.w * va.w;
            o[3][4] += pv.w * vb.x; o[3][5] += pv.w * vb.y; o[3][6] += pv.w * vb.z; o[3][7] += pv.w * vb.w;
        }
    }

    // ---- finalize: divide by l, write out (coalesced float4) ----
#pragma unroll
    for (int r = 0; r < 4; r++) {
        const float inv = 1.0f / l[r];
        const size_t row = (size_t)(qbase + 4 * ty + r) * HDIM + 8 * tx;
        float4 w0, w1;
        w0.x = o[r][0] * inv; w0.y = o[r][1] * inv; w0.z = o[r][2] * inv; w0.w = o[r][3] * inv;
        w1.x = o[r][4] * inv; w1.y = o[r][5] * inv; w1.z = o[r][6] * inv; w1.w = o[r][7] * inv;
        *reinterpret_cast<float4*>(O + row)     = w0;
        *reinterpret_cast<float4*>(O + row + 4) = w1;
    }
}

extern "C" void kernel_launch(void* const* d_in, const int* in_sizes, int n_in,
                              void* d_out, int out_size) {
    const float* q = (const float*)d_in[0];
    const float* k = (const float*)d_in[1];
    const float* v = (const float*)d_in[2];
    float* o = (float*)d_out;
    (void)in_sizes; (void)n_in; (void)out_size;

    cudaFuncSetAttribute(fa_fp32_kernel,
                         cudaFuncAttributeMaxDynamicSharedMemorySize, SMEM_BYTES);
    fa_fp32_kernel<<<N_SEQ / BM, NTHREADS, SMEM_BYTES>>>(q, k, v, o);
}

// round 4
// speedup vs baseline: 3.0103x; 3.0103x over previous
#include <cuda_runtime.h>
#include <cuda_bf16.h>
#include <cstdint>
#include <math.h>

#define N_SEQ 8192
#define HDIM  128
#define BM    64
#define BN    64
#define NTILES (N_SEQ / BN)
#define THREADS 128
#define LOG2E 1.4426950408889634f

// ---- smem byte offsets ----
// bf16 tiles: Q/K rows 64 x 256B (swizzled), Vt rows 128 x 128B (swizzled)
// raw staging: K 32KB linear, V 32KB row-swizzled fp32
#define SM_QHI 0
#define SM_QLO 16384
#define SM_KHI 32768
#define SM_KLO 49152
#define SM_VHI 65536
#define SM_VLO 81920
#define SM_KRAW 98304
#define SM_VRAW 131072
#define SMEM_BYTES 163840

// ---------------- helpers ----------------
__device__ __forceinline__ uint32_t smem_u32(const void* p) {
    uint32_t a;
    asm("{ .reg .u64 t; cvta.to.shared.u64 t, %1; cvt.u32.u64 %0, t; }" : "=r"(a) : "l"(p));
    return a;
}
__device__ __forceinline__ float ex2f(float x) {
    float y; asm("ex2.approx.ftz.f32 %0, %1;" : "=f"(y) : "f"(x)); return y;
}
__device__ __forceinline__ void ldsm_x4(uint32_t* r, uint32_t addr) {
    asm volatile("ldmatrix.sync.aligned.m8n8.x4.shared.b16 {%0,%1,%2,%3}, [%4];"
        : "=r"(r[0]), "=r"(r[1]), "=r"(r[2]), "=r"(r[3]) : "r"(addr));
}
__device__ __forceinline__ void mma_bf16(float* c, const uint32_t* a, const uint32_t* b) {
    asm volatile("mma.sync.aligned.m16n8k16.row.col.f32.bf16.bf16.f32 "
        "{%0,%1,%2,%3}, {%4,%5,%6,%7}, {%8,%9}, {%0,%1,%2,%3};"
        : "+f"(c[0]), "+f"(c[1]), "+f"(c[2]), "+f"(c[3])
        : "r"(a[0]), "r"(a[1]), "r"(a[2]), "r"(a[3]), "r"(b[0]), "r"(b[1]));
}
__device__ __forceinline__ void cp16(uint32_t saddr, const void* g) {
    asm volatile("cp.async.cg.shared.global [%0], [%1], 16;" :: "r"(saddr), "l"(g));
}
#define CP_COMMIT() asm volatile("cp.async.commit_group;" ::: "memory")
#define CP_WAIT0()  asm volatile("cp.async.wait_group 0;" ::: "memory")

__device__ __forceinline__ uint32_t pack_bf2(float a, float b) {
    __nv_bfloat162 t = __floats2bfloat162_rn(a, b);
    return *reinterpret_cast<uint32_t*>(&t);
}
// split x into bf16-hi (rn, returned as low-16 bits) and fp32 residual
__device__ __forceinline__ void bfsplit(float x, uint32_t& hi16, float& lo) {
    uint32_t u = __float_as_uint(x);
    uint32_t h = (u + 0x7FFFu + ((u >> 16) & 1u)) & 0xFFFF0000u;
    hi16 = h >> 16;
    lo = x - __uint_as_float(h);
}

// convert+store a float4 into hi/lo bf16 tiles with 256B-row chunk swizzle
__device__ __forceinline__ void cvt_store256(char* smem, int hibase, int lobase,
                                             int r, int c4, float4 v) {
    uint32_t h0, h1, h2, h3; float l0, l1, l2, l3;
    bfsplit(v.x, h0, l0); bfsplit(v.y, h1, l1);
    bfsplit(v.z, h2, l2); bfsplit(v.w, h3, l3);
    uint2 hi = make_uint2(h0 | (h1 << 16), h2 | (h3 << 16));
    uint2 lo = make_uint2(pack_bf2(l0, l1), pack_bf2(l2, l3));
    int ch = c4 >> 1, s8 = (c4 & 1) * 8;
    uint32_t off = (uint32_t)(r * 256 + ((ch ^ (r & 7)) << 4) + s8);
    *reinterpret_cast<uint2*>(smem + hibase + off) = hi;
    *reinterpret_cast<uint2*>(smem + lobase + off) = lo;
}

// --------------------------------------------------------------------------
__global__ __launch_bounds__(THREADS, 1)
void fa_hmma_kernel(const float* __restrict__ Q, const float* __restrict__ K,
                    const float* __restrict__ V, float* __restrict__ O) {
    extern __shared__ char smem[];
    const uint32_t sb = smem_u32(smem);
    const int tid  = threadIdx.x;
    const int lane = tid & 31;
    const int wid  = tid >> 5;      // 0..3
    const int m0   = wid * 16;      // warp's 16 q-rows within the 64-row block
    const int qbase = blockIdx.x * BM;
    const int l7  = lane & 7;
    const int sub = lane >> 3;      // 0..3  (ldmatrix address group)

    // ---- prefetch tile 0 raw K/V via cp.async ----
    {
        const char* Kg = (const char*)K;
        const char* Vg = (const char*)V;
#pragma unroll
        for (int it = 0; it < 16; it++) {
            int task = it * THREADS + tid;              // 0..2047 (16B units)
            cp16(sb + SM_KRAW + task * 16, Kg + task * 16);
            int r = task >> 5, c = task & 31;           // V: row-keyed chunk swizzle
            cp16(sb + SM_VRAW + r * 512 + ((c ^ ((r >> 1) & 7)) << 4), Vg + task * 16);
        }
        CP_COMMIT();
    }

    // ---- convert Q once (from global, coalesced) ----
    {
        const float* Qg = Q + (size_t)qbase * HDIM;
#pragma unroll
        for (int it = 0; it < 16; it++) {
            int task = it * THREADS + tid;
            int r = task >> 5, c4 = task & 31;
            float4 v = *reinterpret_cast<const float4*>(Qg + r * HDIM + c4 * 4);
            cvt_store256(smem, SM_QHI, SM_QLO, r, c4, v);
        }
    }

    float oa[16][4];
    float mrow[2] = {-INFINITY, -INFINITY};
    float lrow[2] = {0.f, 0.f};
#pragma unroll
    for (int nb = 0; nb < 16; nb++)
#pragma unroll
        for (int i = 0; i < 4; i++) oa[nb][i] = 0.f;

    for (int t = 0; t < NTILES; t++) {
        CP_WAIT0();
        __syncthreads();

        // ---- convert K tile: raw fp32 (linear) -> hi/lo bf16 (swizzled) ----
#pragma unroll
        for (int it = 0; it < 16; it++) {
            int task = it * THREADS + tid;
            int r = task >> 5, c4 = task & 31;
            float4 v = *reinterpret_cast<const float4*>(smem + SM_KRAW + task * 16);
            cvt_store256(smem, SM_KHI, SM_KLO, r, c4, v);
        }
        // ---- convert V tile: raw (row-swizzled) -> transposed Vt[d][j] hi/lo ----
#pragma unroll
        for (int it = 0; it < 8; it++) {
            int task = it * THREADS + tid;
            int jp = task & 31, c4 = task >> 5;   // j-pair 2jp, d-group 4*c4
            uint32_t rowoff = (uint32_t)((2 * jp) * 512 + ((c4 ^ (jp & 7)) << 4));
            float4 a = *reinterpret_cast<const float4*>(smem + SM_VRAW + rowoff);
            float4 b = *reinterpret_cast<const float4*>(smem + SM_VRAW + rowoff + 512);
            float av[4] = {a.x, a.y, a.z, a.w};
            float bv[4] = {b.x, b.y, b.z, b.w};
#pragma unroll
            for (int u = 0; u < 4; u++) {
                int d = 4 * c4 + u;
                uint32_t h0, h1; float lo0, lo1;
                bfsplit(av[u], h0, lo0);
                bfsplit(bv[u], h1, lo1);
                uint32_t off = (uint32_t)(d * 128 + (((jp >> 2) ^ (d & 7)) << 4) + (jp & 3) * 4);
                *reinterpret_cast<uint32_t*>(smem + SM_VHI + off) = h0 | (h1 << 16);
                *reinterpret_cast<uint32_t*>(smem + SM_VLO + off) = pack_bf2(lo0, lo1);
            }
        }
        __syncthreads();

        // ---- prefetch next tile during compute ----
        if (t + 1 < NTILES) {
            const char* Kg = (const char*)(K + (size_t)(t + 1) * BN * HDIM);
            const char* Vg = (const char*)(V + (size_t)(t + 1) * BN * HDIM);
#pragma unroll
            for (int it = 0; it < 16; it++) {
                int task = it * THREADS + tid;
                cp16(sb + SM_KRAW + task * 16, Kg + task * 16);
                int r = task >> 5, c = task & 31;
                cp16(sb + SM_VRAW + r * 512 + ((c ^ ((r >> 1) & 7)) << 4), Vg + task * 16);
            }
            CP_COMMIT();
        }

        // ---- S = Q K^T  (3-term bf16 split, fp32 accum) ----
        float sa[8][4];
#pragma unroll
        for (int nb = 0; nb < 8; nb++)
#pragma unroll
            for (int i = 0; i < 4; i++) sa[nb][i] = 0.f;

#pragma unroll
        for (int ks = 0; ks < 8; ks++) {
            uint32_t qh[4], ql[4];
            {
                int r = m0 + l7 + (sub & 1) * 8;
                int ch = ks * 2 + (sub >> 1);
                uint32_t a = sb + SM_QHI + r * 256 + ((ch ^ (r & 7)) << 4);
                ldsm_x4(qh, a);
                ldsm_x4(ql, a + (SM_QLO - SM_QHI));
            }
#pragma unroll
            for (int nbp = 0; nbp < 4; nbp++) {
                uint32_t kh[4], kl[4];
                int r = nbp * 16 + l7 + (sub >> 1) * 8;
                int ch = ks * 2 + (sub & 1);
                uint32_t a = sb + SM_KHI + r * 256 + ((ch ^ (r & 7)) << 4);
                ldsm_x4(kh, a);
                ldsm_x4(kl, a + (SM_KLO - SM_KHI));
                mma_bf16(sa[2 * nbp],     qh, kh);
                mma_bf16(sa[2 * nbp + 1], qh, kh + 2);
                mma_bf16(sa[2 * nbp],     qh, kl);
                mma_bf16(sa[2 * nbp + 1], qh, kl + 2);
                mma_bf16(sa[2 * nbp],     ql, kh);
                mma_bf16(sa[2 * nbp + 1], ql, kh + 2);
            }
        }

        // ---- online softmax (rows: r0 = m0+lane/4, r1 = r0+8) ----
        float rm0 = sa[0][0], rm1 = sa[0][2];
#pragma unroll
        for (int nb = 0; nb < 8; nb++) {
            rm0 = fmaxf(rm0, fmaxf(sa[nb][0], sa[nb][1]));
            rm1 = fmaxf(rm1, fmaxf(sa[nb][2], sa[nb][3]));
        }
        rm0 = fmaxf(rm0, __shfl_xor_sync(0xffffffffu, rm0, 1));
        rm0 = fmaxf(rm0, __shfl_xor_sync(0xffffffffu, rm0, 2));
        rm1 = fmaxf(rm1, __shfl_xor_sync(0xffffffffu, rm1, 1));
        rm1 = fmaxf(rm1, __shfl_xor_sync(0xffffffffu, rm1, 2));

        const float mn0 = fmaxf(mrow[0], rm0);
        const float mn1 = fmaxf(mrow[1], rm1);
        const float al0 = ex2f((mrow[0] - mn0) * LOG2E);
        const float al1 = ex2f((mrow[1] - mn1) * LOG2E);

        float rs0 = 0.f, rs1 = 0.f;
#pragma unroll
        for (int nb = 0; nb < 8; nb++) {
            sa[nb][0] = ex2f((sa[nb][0] - mn0) * LOG2E); rs0 += sa[nb][0];
            sa[nb][1] = ex2f((sa[nb][1] - mn0) * LOG2E); rs0 += sa[nb][1];
            sa[nb][2] = ex2f((sa[nb][2] - mn1) * LOG2E); rs1 += sa[nb][2];
            sa[nb][3] = ex2f((sa[nb][3] - mn1) * LOG2E); rs1 += sa[nb][3];
        }
        rs0 += __shfl_xor_sync(0xffffffffu, rs0, 1);
        rs0 += __shfl_xor_sync(0xffffffffu, rs0, 2);
        rs1 += __shfl_xor_sync(0xffffffffu, rs1, 1);
        rs1 += __shfl_xor_sync(0xffffffffu, rs1, 2);
        lrow[0] = lrow[0] * al0 + rs0;  mrow[0] = mn0;
        lrow[1] = lrow[1] * al1 + rs1;  mrow[1] = mn1;

#pragma unroll
        for (int nb = 0; nb < 16; nb++) {
            oa[nb][0] *= al0; oa[nb][1] *= al0;
            oa[nb][2] *= al1; oa[nb][3] *= al1;
        }

        // ---- O += P V  (P from registers, 3-term split) ----
#pragma unroll
        for (int ks = 0; ks < 4; ks++) {
            uint32_t ph[4], pl[4];
#pragma unroll
            for (int h = 0; h < 2; h++) {
                float p0 = sa[2 * ks + h][0], p1 = sa[2 * ks + h][1];
                float p2 = sa[2 * ks + h][2], p3 = sa[2 * ks + h][3];
                uint32_t h0, h1, h2, h3; float l0, l1, l2, l3;
                bfsplit(p0, h0, l0); bfsplit(p1, h1, l1);
                bfsplit(p2, h2, l2); bfsplit(p3, h3, l3);
                ph[2 * h]     = h0 | (h1 << 16);
                ph[2 * h + 1] = h2 | (h3 << 16);
                pl[2 * h]     = pack_bf2(l0, l1);
                pl[2 * h + 1] = pack_bf2(l2, l3);
            }
#pragma unroll
            for (int nbp = 0; nbp < 8; nbp++) {
                uint32_t vh[4], vl[4];
                int r = nbp * 16 + l7 + (sub >> 1) * 8;
                int ch = ks * 2 + (sub & 1);
                uint32_t a = sb + SM_VHI + r * 128 + ((ch ^ (r & 7)) << 4);
                ldsm_x4(vh, a);
                ldsm_x4(vl, a + (SM_VLO - SM_VHI));
                mma_bf16(oa[2 * nbp],     ph, vh);
                mma_bf16(oa[2 * nbp + 1], ph, vh + 2);
                mma_bf16(oa[2 * nbp],     ph, vl);
                mma_bf16(oa[2 * nbp + 1], ph, vl + 2);
                mma_bf16(oa[2 * nbp],     pl, vh);
                mma_bf16(oa[2 * nbp + 1], pl, vh + 2);
            }
        }
    }

    // ---- epilogue ----
    const float inv0 = 1.0f / lrow[0];
    const float inv1 = 1.0f / lrow[1];
    const int r0 = qbase + m0 + (lane >> 2);
    float* O0 = O + (size_t)r0 * HDIM;
    float* O1 = O0 + 8 * HDIM;
    const int cb = (lane & 3) * 2;
#pragma unroll
    for (int nb = 0; nb < 16; nb++) {
        *reinterpret_cast<float2*>(O0 + nb * 8 + cb) =
            make_float2(oa[nb][0] * inv0, oa[nb][1] * inv0);
        *reinterpret_cast<float2*>(O1 + nb * 8 + cb) =
            make_float2(oa[nb][2] * inv1, oa[nb][3] * inv1);
    }
}

extern "C" void kernel_launch(void* const* d_in, const int* in_sizes, int n_in,
                              void* d_out, int out_size) {
    const float* q = (const float*)d_in[0];
    const float* k = (const float*)d_in[1];
    const float* v = (const float*)d_in[2];
    float* o = (float*)d_out;
    (void)in_sizes; (void)n_in; (void)out_size;

    cudaFuncSetAttribute(fa_hmma_kernel,
                         cudaFuncAttributeMaxDynamicSharedMemorySize, SMEM_BYTES);
    fa_hmma_kernel<<<N_SEQ / BM, THREADS, SMEM_BYTES>>>(q, k, v, o);
}

// round 6
// speedup vs baseline: 3.1504x; 1.0465x over previous
#include <cuda_runtime.h>
#include <cuda_bf16.h>
#include <cstdint>
#include <math.h>

#define N_SEQ 8192
#define HDIM  128
#define BM    64
#define BN    64
#define NTILES (N_SEQ / BN)
#define THREADS 256
#define LOG2E 1.4426950408889634f

// ---- smem byte offsets ----
#define SM_QHI 0
#define SM_QLO 16384
#define SM_KHI 32768
#define SM_KLO 49152
#define SM_VHI 65536
#define SM_VLO 81920
#define SM_KRAW 98304          // raw K staging; reused as O-exchange buffer in epilogue
#define SM_VRAW 131072
#define SM_PMAX 163840         // float[2][64]
#define SM_PSUM 164352         // float[2][64]
#define SMEM_BYTES 164864
#define XBUF_STRIDE 132        // floats per row in O-exchange buffer (bank-shifted)

// ---------------- helpers ----------------
__device__ __forceinline__ uint32_t smem_u32(const void* p) {
    uint32_t a;
    asm("{ .reg .u64 t; cvta.to.shared.u64 t, %1; cvt.u32.u64 %0, t; }" : "=r"(a) : "l"(p));
    return a;
}
__device__ __forceinline__ float ex2f(float x) {
    float y; asm("ex2.approx.ftz.f32 %0, %1;" : "=f"(y) : "f"(x)); return y;
}
__device__ __forceinline__ void ldsm_x4(uint32_t* r, uint32_t addr) {
    asm volatile("ldmatrix.sync.aligned.m8n8.x4.shared.b16 {%0,%1,%2,%3}, [%4];"
        : "=r"(r[0]), "=r"(r[1]), "=r"(r[2]), "=r"(r[3]) : "r"(addr));
}
__device__ __forceinline__ void mma_bf16(float* c, const uint32_t* a, const uint32_t* b) {
    asm volatile("mma.sync.aligned.m16n8k16.row.col.f32.bf16.bf16.f32 "
        "{%0,%1,%2,%3}, {%4,%5,%6,%7}, {%8,%9}, {%0,%1,%2,%3};"
        : "+f"(c[0]), "+f"(c[1]), "+f"(c[2]), "+f"(c[3])
        : "r"(a[0]), "r"(a[1]), "r"(a[2]), "r"(a[3]), "r"(b[0]), "r"(b[1]));
}
__device__ __forceinline__ void cp16(uint32_t saddr, const void* g) {
    asm volatile("cp.async.cg.shared.global [%0], [%1], 16;" :: "r"(saddr), "l"(g));
}
#define CP_COMMIT() asm volatile("cp.async.commit_group;" ::: "memory")
#define CP_WAIT0()  asm volatile("cp.async.wait_group 0;" ::: "memory")

__device__ __forceinline__ uint32_t pack_bf2(float a, float b) {
    __nv_bfloat162 t = __floats2bfloat162_rn(a, b);
    return *reinterpret_cast<uint32_t*>(&t);
}
__device__ __forceinline__ void bfsplit(float x, uint32_t& hi16, float& lo) {
    uint32_t u = __float_as_uint(x);
    uint32_t h = (u + 0x7FFFu + ((u >> 16) & 1u)) & 0xFFFF0000u;
    hi16 = h >> 16;
    lo = x - __uint_as_float(h);
}

__device__ __forceinline__ void cvt_store256(char* smem, int hibase, int lobase,
                                             int r, int c4, float4 v) {
    uint32_t h0, h1, h2, h3; float l0, l1, l2, l3;
    bfsplit(v.x, h0, l0); bfsplit(v.y, h1, l1);
    bfsplit(v.z, h2, l2); bfsplit(v.w, h3, l3);
    uint2 hi = make_uint2(h0 | (h1 << 16), h2 | (h3 << 16));
    uint2 lo = make_uint2(pack_bf2(l0, l1), pack_bf2(l2, l3));
    int ch = c4 >> 1, s8 = (c4 & 1) * 8;
    uint32_t off = (uint32_t)(r * 256 + ((ch ^ (r & 7)) << 4) + s8);
    *reinterpret_cast<uint2*>(smem + hibase + off) = hi;
    *reinterpret_cast<uint2*>(smem + lobase + off) = lo;
}

// --------------------------------------------------------------------------
__global__ __launch_bounds__(THREADS, 1)
void fa_hmma_kernel(const float* __restrict__ Q, const float* __restrict__ K,
                    const float* __restrict__ V, float* __restrict__ O) {
    extern __shared__ char smem[];
    const uint32_t sb = smem_u32(smem);
    const int tid  = threadIdx.x;
    const int lane = tid & 31;
    const int wid  = tid >> 5;        // 0..7
    const int mw   = wid & 3;         // row group
    const int nh   = wid >> 2;        // N-half (0: cols 0-31, 1: cols 32-63)
    const int m0   = mw * 16;
    const int qbase = blockIdx.x * BM;
    const int l7  = lane & 7;
    const int sub = lane >> 3;

    float* pmax = (float*)(smem + SM_PMAX);
    float* psum = (float*)(smem + SM_PSUM);

    // ---- prefetch tile 0 raw K/V ----
    {
        const char* Kg = (const char*)K;
        const char* Vg = (const char*)V;
#pragma unroll
        for (int it = 0; it < 8; it++) {
            int task = it * THREADS + tid;
            cp16(sb + SM_KRAW + task * 16, Kg + task * 16);
            int r = task >> 5, c = task & 31;
            cp16(sb + SM_VRAW + r * 512 + ((c ^ ((r >> 1) & 7)) << 4), Vg + task * 16);
        }
        CP_COMMIT();
    }

    // ---- convert Q once ----
    {
        const float* Qg = Q + (size_t)qbase * HDIM;
#pragma unroll
        for (int it = 0; it < 8; it++) {
            int task = it * THREADS + tid;
            int r = task >> 5, c4 = task & 31;
            float4 v = *reinterpret_cast<const float4*>(Qg + r * HDIM + c4 * 4);
            cvt_store256(smem, SM_QHI, SM_QLO, r, c4, v);
        }
    }

    float oa[16][4];
    float mrow[2] = {-INFINITY, -INFINITY};
    float lrow[2] = {0.f, 0.f};
#pragma unroll
    for (int nb = 0; nb < 16; nb++)
#pragma unroll
        for (int i = 0; i < 4; i++) oa[nb][i] = 0.f;

    const int xr0 = m0 + (lane >> 2);      // absolute block row of accum row 0
    const int xr1 = xr0 + 8;

    for (int t = 0; t < NTILES; t++) {
        CP_WAIT0();
        __syncthreads();

        // ---- convert K tile ----
#pragma unroll
        for (int it = 0; it < 8; it++) {
            int task = it * THREADS + tid;
            int r = task >> 5, c4 = task & 31;
            float4 v = *reinterpret_cast<const float4*>(smem + SM_KRAW + task * 16);
            cvt_store256(smem, SM_KHI, SM_KLO, r, c4, v);
        }
        // ---- convert V tile -> transposed Vt[d][j] ----
#pragma unroll
        for (int it = 0; it < 4; it++) {
            int task = it * THREADS + tid;
            int jp = task & 31, c4 = task >> 5;
            uint32_t rowoff = (uint32_t)((2 * jp) * 512 + ((c4 ^ (jp & 7)) << 4));
            float4 a = *reinterpret_cast<const float4*>(smem + SM_VRAW + rowoff);
            float4 b = *reinterpret_cast<const float4*>(smem + SM_VRAW + rowoff + 512);
            float av[4] = {a.x, a.y, a.z, a.w};
            float bv[4] = {b.x, b.y, b.z, b.w};
#pragma unroll
            for (int u = 0; u < 4; u++) {
                int d = 4 * c4 + u;
                uint32_t h0, h1; float lo0, lo1;
                bfsplit(av[u], h0, lo0);
                bfsplit(bv[u], h1, lo1);
                uint32_t off = (uint32_t)(d * 128 + (((jp >> 2) ^ (d & 7)) << 4) + (jp & 3) * 4);
                *reinterpret_cast<uint32_t*>(smem + SM_VHI + off) = h0 | (h1 << 16);
                *reinterpret_cast<uint32_t*>(smem + SM_VLO + off) = pack_bf2(lo0, lo1);
            }
        }
        __syncthreads();

        // ---- prefetch next tile ----
        if (t + 1 < NTILES) {
            const char* Kg = (const char*)(K + (size_t)(t + 1) * BN * HDIM);
            const char* Vg = (const char*)(V + (size_t)(t + 1) * BN * HDIM);
#pragma unroll
            for (int it = 0; it < 8; it++) {
                int task = it * THREADS + tid;
                cp16(sb + SM_KRAW + task * 16, Kg + task * 16);
                int r = task >> 5, c = task & 31;
                cp16(sb + SM_VRAW + r * 512 + ((c ^ ((r >> 1) & 7)) << 4), Vg + task * 16);
            }
            CP_COMMIT();
        }

        // ---- S = Q K^T for this warp's 32-col half ----
        float sa[4][4];
#pragma unroll
        for (int nb = 0; nb < 4; nb++)
#pragma unroll
            for (int i = 0; i < 4; i++) sa[nb][i] = 0.f;

#pragma unroll
        for (int ks = 0; ks < 8; ks++) {
            uint32_t qh[4], ql[4];
            {
                int r = m0 + l7 + (sub & 1) * 8;
                int ch = ks * 2 + (sub >> 1);
                uint32_t a = sb + SM_QHI + r * 256 + ((ch ^ (r & 7)) << 4);
                ldsm_x4(qh, a);
                ldsm_x4(ql, a + (SM_QLO - SM_QHI));
            }
#pragma unroll
            for (int nbp = 0; nbp < 2; nbp++) {
                uint32_t kh[4], kl[4];
                int r = nh * 32 + nbp * 16 + l7 + (sub >> 1) * 8;
                int ch = ks * 2 + (sub & 1);
                uint32_t a = sb + SM_KHI + r * 256 + ((ch ^ (r & 7)) << 4);
                ldsm_x4(kh, a);
                ldsm_x4(kl, a + (SM_KLO - SM_KHI));
                mma_bf16(sa[2 * nbp],     qh, kh);
                mma_bf16(sa[2 * nbp + 1], qh, kh + 2);
                mma_bf16(sa[2 * nbp],     qh, kl);
                mma_bf16(sa[2 * nbp + 1], qh, kl + 2);
                mma_bf16(sa[2 * nbp],     ql, kh);
                mma_bf16(sa[2 * nbp + 1], ql, kh + 2);
            }
        }

        // ---- partial row max over this warp's 32 cols ----
        float rm0 = sa[0][0], rm1 = sa[0][2];
#pragma unroll
        for (int nb = 0; nb < 4; nb++) {
            rm0 = fmaxf(rm0, fmaxf(sa[nb][0], sa[nb][1]));
            rm1 = fmaxf(rm1, fmaxf(sa[nb][2], sa[nb][3]));
        }
        rm0 = fmaxf(rm0, __shfl_xor_sync(0xffffffffu, rm0, 1));
        rm0 = fmaxf(rm0, __shfl_xor_sync(0xffffffffu, rm0, 2));
        rm1 = fmaxf(rm1, __shfl_xor_sync(0xffffffffu, rm1, 1));
        rm1 = fmaxf(rm1, __shfl_xor_sync(0xffffffffu, rm1, 2));

        // exchange max with pair warp
        if ((lane & 3) == 0) {
            pmax[nh * 64 + xr0] = rm0;
            pmax[nh * 64 + xr1] = rm1;
        }
        __syncthreads();
        rm0 = fmaxf(rm0, pmax[(1 - nh) * 64 + xr0]);
        rm1 = fmaxf(rm1, pmax[(1 - nh) * 64 + xr1]);

        const float mn0 = fmaxf(mrow[0], rm0);
        const float mn1 = fmaxf(mrow[1], rm1);
        const float al0 = ex2f((mrow[0] - mn0) * LOG2E);
        const float al1 = ex2f((mrow[1] - mn1) * LOG2E);

        float rs0 = 0.f, rs1 = 0.f;
#pragma unroll
        for (int nb = 0; nb < 4; nb++) {
            sa[nb][0] = ex2f((sa[nb][0] - mn0) * LOG2E); rs0 += sa[nb][0];
            sa[nb][1] = ex2f((sa[nb][1] - mn0) * LOG2E); rs0 += sa[nb][1];
            sa[nb][2] = ex2f((sa[nb][2] - mn1) * LOG2E); rs1 += sa[nb][2];
            sa[nb][3] = ex2f((sa[nb][3] - mn1) * LOG2E); rs1 += sa[nb][3];
        }
        rs0 += __shfl_xor_sync(0xffffffffu, rs0, 1);
        rs0 += __shfl_xor_sync(0xffffffffu, rs0, 2);
        rs1 += __shfl_xor_sync(0xffffffffu, rs1, 1);
        rs1 += __shfl_xor_sync(0xffffffffu, rs1, 2);

        if ((lane & 3) == 0) {
            psum[nh * 64 + xr0] = rs0;
            psum[nh * 64 + xr1] = rs1;
        }
        __syncthreads();
        rs0 += psum[(1 - nh) * 64 + xr0];
        rs1 += psum[(1 - nh) * 64 + xr1];

        lrow[0] = lrow[0] * al0 + rs0;  mrow[0] = mn0;
        lrow[1] = lrow[1] * al1 + rs1;  mrow[1] = mn1;

#pragma unroll
        for (int nb = 0; nb < 16; nb++) {
            oa[nb][0] *= al0; oa[nb][1] *= al0;
            oa[nb][2] *= al1; oa[nb][3] *= al1;
        }

        // ---- O += P V over this warp's 32-j half ----
#pragma unroll
        for (int ks = 0; ks < 2; ks++) {
            uint32_t ph[4], pl[4];
#pragma unroll
            for (int h = 0; h < 2; h++) {
                float p0 = sa[2 * ks + h][0], p1 = sa[2 * ks + h][1];
                float p2 = sa[2 * ks + h][2], p3 = sa[2 * ks + h][3];
                uint32_t h0, h1, h2, h3; float l0, l1, l2, l3;
                bfsplit(p0, h0, l0); bfsplit(p1, h1, l1);
                bfsplit(p2, h2, l2); bfsplit(p3, h3, l3);
                ph[2 * h]     = h0 | (h1 << 16);
                ph[2 * h + 1] = h2 | (h3 << 16);
                pl[2 * h]     = pack_bf2(l0, l1);
                pl[2 * h + 1] = pack_bf2(l2, l3);
            }
            const int chb = nh * 4 + ks * 2 + (sub & 1);
#pragma unroll
            for (int nbp = 0; nbp < 8; nbp++) {
                uint32_t vh[4], vl[4];
                int r = nbp * 16 + l7 + (sub >> 1) * 8;
                uint32_t a = sb + SM_VHI + r * 128 + ((chb ^ (r & 7)) << 4);
                ldsm_x4(vh, a);
                ldsm_x4(vl, a + (SM_VLO - SM_VHI));
                mma_bf16(oa[2 * nbp],     ph, vh);
                mma_bf16(oa[2 * nbp + 1], ph, vh + 2);
                mma_bf16(oa[2 * nbp],     ph, vl);
                mma_bf16(oa[2 * nbp + 1], ph, vl + 2);
                mma_bf16(oa[2 * nbp],     pl, vh);
                mma_bf16(oa[2 * nbp + 1], pl, vh + 2);
            }
        }
    }

    // ---- epilogue: sum partial O across warp pairs, scale, store ----
    float* xbuf = (float*)(smem + SM_KRAW);
    const int cb = (lane & 3) * 2;
    __syncthreads();
    if (nh == 1) {
#pragma unroll
        for (int nb = 0; nb < 16; nb++) {
            *reinterpret_cast<float2*>(xbuf + xr0 * XBUF_STRIDE + nb * 8 + cb) =
                make_float2(oa[nb][0], oa[nb][1]);
            *reinterpret_cast<float2*>(xbuf + xr1 * XBUF_STRIDE + nb * 8 + cb) =
                make_float2(oa[nb][2], oa[nb][3]);
        }
    }
    __syncthreads();
    if (nh == 0) {
        const float inv0 = 1.0f / lrow[0];
        const float inv1 = 1.0f / lrow[1];
        float* O0 = O + (size_t)(qbase + xr0) * HDIM;
        float* O1 = O + (size_t)(qbase + xr1) * HDIM;
#pragma unroll
        for (int nb = 0; nb < 16; nb++) {
            float2 x0 = *reinterpret_cast<float2*>(xbuf + xr0 * XBUF_STRIDE + nb * 8 + cb);
            float2 x1 = *reinterpret_cast<float2*>(xbuf + xr1 * XBUF_STRIDE + nb * 8 + cb);
            *reinterpret_cast<float2*>(O0 + nb * 8 + cb) =
                make_float2((oa[nb][0] + x0.x) * inv0, (oa[nb][1] + x0.y) * inv0);
            *reinterpret_cast<float2*>(O1 + nb * 8 + cb) =
                make_float2((oa[nb][2] + x1.x) * inv1, (oa[nb][3] + x1.y) * inv1);
        }
    }
}

extern "C" void kernel_launch(void* const* d_in, const int* in_sizes, int n_in,
                              void* d_out, int out_size) {
    const float* q = (const float*)d_in[0];
    const float* k = (const float*)d_in[1];
    const float* v = (const float*)d_in[2];
    float* o = (float*)d_out;
    (void)in_sizes; (void)n_in; (void)out_size;

    cudaFuncSetAttribute(fa_hmma_kernel,
                         cudaFuncAttributeMaxDynamicSharedMemorySize, SMEM_BYTES);
    fa_hmma_kernel<<<N_SEQ / BM, THREADS, SMEM_BYTES>>>(q, k, v, o);
}

// round 9
// speedup vs baseline: 4.2441x; 1.3472x over previous
#include <cuda_runtime.h>
#include <cuda_bf16.h>
#include <cstdint>
#include <math.h>

#define N_SEQ 8192
#define HDIM  128
#define BM    128
#define BN    64
#define NTILES (N_SEQ / BN)      // 128
#define HALF_TILES (NTILES / 2)  // 64 per KV-half
#define THREADS 256
#define LOG2E 1.4426950408889634f

// ---- smem byte offsets ----
#define SM_QHI 0            // 128 rows x 256B
#define SM_QLO 32768
#define SM_KHI 65536        // 64 rows x 256B
#define SM_KLO 81920
#define SM_VHI 98304        // 128 d-rows x 128B
#define SM_VLO 114688
#define SM_KRAW 131072      // 32KB raw K staging
#define SM_VRAW 163840      // 32KB raw V staging
#define SMEM_BYTES 196608

// split-KV scratch
__device__ float g_A[2 * N_SEQ * HDIM];
__device__ float g_M[2 * N_SEQ];
__device__ float g_L[2 * N_SEQ];

// ---------------- helpers ----------------
__device__ __forceinline__ uint32_t smem_u32(const void* p) {
    uint32_t a;
    asm("{ .reg .u64 t; cvta.to.shared.u64 t, %1; cvt.u32.u64 %0, t; }" : "=r"(a) : "l"(p));
    return a;
}
__device__ __forceinline__ float ex2f(float x) {
    float y; asm("ex2.approx.ftz.f32 %0, %1;" : "=f"(y) : "f"(x)); return y;
}
__device__ __forceinline__ void ldsm_x4(uint32_t* r, uint32_t addr) {
    asm volatile("ldmatrix.sync.aligned.m8n8.x4.shared.b16 {%0,%1,%2,%3}, [%4];"
        : "=r"(r[0]), "=r"(r[1]), "=r"(r[2]), "=r"(r[3]) : "r"(addr));
}
__device__ __forceinline__ void mma_bf16(float* c, const uint32_t* a, const uint32_t* b) {
    asm volatile("mma.sync.aligned.m16n8k16.row.col.f32.bf16.bf16.f32 "
        "{%0,%1,%2,%3}, {%4,%5,%6,%7}, {%8,%9}, {%0,%1,%2,%3};"
        : "+f"(c[0]), "+f"(c[1]), "+f"(c[2]), "+f"(c[3])
        : "r"(a[0]), "r"(a[1]), "r"(a[2]), "r"(a[3]), "r"(b[0]), "r"(b[1]));
}
__device__ __forceinline__ void cp16(uint32_t saddr, const void* g) {
    asm volatile("cp.async.cg.shared.global [%0], [%1], 16;" :: "r"(saddr), "l"(g));
}
#define CP_COMMIT() asm volatile("cp.async.commit_group;" ::: "memory")
#define CP_WAIT0()  asm volatile("cp.async.wait_group 0;" ::: "memory")

__device__ __forceinline__ uint32_t pack_bf2(float a, float b) {
    __nv_bfloat162 t = __floats2bfloat162_rn(a, b);
    return *reinterpret_cast<uint32_t*>(&t);
}
__device__ __forceinline__ void bfsplit(float x, uint32_t& hi16, float& lo) {
    uint32_t u = __float_as_uint(x);
    uint32_t h = (u + 0x7FFFu + ((u >> 16) & 1u)) & 0xFFFF0000u;
    hi16 = h >> 16;
    lo = x - __uint_as_float(h);
}
__device__ __forceinline__ void cvt_store256(char* smem, int hibase, int lobase,
                                             int r, int c4, float4 v) {
    uint32_t h0, h1, h2, h3; float l0, l1, l2, l3;
    bfsplit(v.x, h0, l0); bfsplit(v.y, h1, l1);
    bfsplit(v.z, h2, l2); bfsplit(v.w, h3, l3);
    uint2 hi = make_uint2(h0 | (h1 << 16), h2 | (h3 << 16));
    uint2 lo = make_uint2(pack_bf2(l0, l1), pack_bf2(l2, l3));
    int ch = c4 >> 1, s8 = (c4 & 1) * 8;
    uint32_t off = (uint32_t)(r * 256 + ((ch ^ (r & 7)) << 4) + s8);
    *reinterpret_cast<uint2*>(smem + hibase + off) = hi;
    *reinterpret_cast<uint2*>(smem + lobase + off) = lo;
}

// --------------------------------------------------------------------------
__global__ __launch_bounds__(THREADS, 1)
void fa_hmma_kernel(const float* __restrict__ Q, const float* __restrict__ K,
                    const float* __restrict__ V) {
    extern __shared__ char smem[];
    const uint32_t sb = smem_u32(smem);
    const int tid  = threadIdx.x;
    const int lane = tid & 31;
    const int wid  = tid >> 5;        // 0..7, owns q-rows [16w, 16w+16)
    const int m0   = wid * 16;
    const int qb   = blockIdx.x >> 1;
    const int kvh  = blockIdx.x & 1;  // KV half
    const int qbase = qb * BM;
    const int t0   = kvh * HALF_TILES;
    const int l7  = lane & 7;
    const int sub = lane >> 3;

    // ---- prefetch first raw K/V tile of this half ----
    {
        const char* Kg = (const char*)(K + (size_t)t0 * BN * HDIM);
        const char* Vg = (const char*)(V + (size_t)t0 * BN * HDIM);
#pragma unroll
        for (int it = 0; it < 8; it++) {
            int task = it * THREADS + tid;
            cp16(sb + SM_KRAW + task * 16, Kg + task * 16);
            int r = task >> 5, c = task & 31;
            cp16(sb + SM_VRAW + r * 512 + ((c ^ ((r >> 1) & 7)) << 4), Vg + task * 16);
        }
        CP_COMMIT();
    }

    // ---- convert Q once (128 rows) ----
    {
        const float* Qg = Q + (size_t)qbase * HDIM;
#pragma unroll
        for (int it = 0; it < 16; it++) {
            int task = it * THREADS + tid;
            int r = task >> 5, c4 = task & 31;
            float4 v = *reinterpret_cast<const float4*>(Qg + r * HDIM + c4 * 4);
            cvt_store256(smem, SM_QHI, SM_QLO, r, c4, v);
        }
    }

    float oa[16][4];
    float mrow[2] = {-INFINITY, -INFINITY};
    float lrow[2] = {0.f, 0.f};
#pragma unroll
    for (int nb = 0; nb < 16; nb++)
#pragma unroll
        for (int i = 0; i < 4; i++) oa[nb][i] = 0.f;

    for (int tt = 0; tt < HALF_TILES; tt++) {
        const int t = t0 + tt;
        CP_WAIT0();
        __syncthreads();

        // ---- convert K tile ----
#pragma unroll
        for (int it = 0; it < 8; it++) {
            int task = it * THREADS + tid;
            int r = task >> 5, c4 = task & 31;
            float4 v = *reinterpret_cast<const float4*>(smem + SM_KRAW + task * 16);
            cvt_store256(smem, SM_KHI, SM_KLO, r, c4, v);
        }
        // ---- convert V tile -> transposed Vt[d][j] ----
#pragma unroll
        for (int it = 0; it < 4; it++) {
            int task = it * THREADS + tid;
            int jp = task & 31, c4 = task >> 5;
            uint32_t rowoff = (uint32_t)((2 * jp) * 512 + ((c4 ^ (jp & 7)) << 4));
            float4 a = *reinterpret_cast<const float4*>(smem + SM_VRAW + rowoff);
            float4 b = *reinterpret_cast<const float4*>(smem + SM_VRAW + rowoff + 512);
            float av[4] = {a.x, a.y, a.z, a.w};
            float bv[4] = {b.x, b.y, b.z, b.w};
#pragma unroll
            for (int u = 0; u < 4; u++) {
                int d = 4 * c4 + u;
                uint32_t h0, h1; float lo0, lo1;
                bfsplit(av[u], h0, lo0);
                bfsplit(bv[u], h1, lo1);
                uint32_t off = (uint32_t)(d * 128 + (((jp >> 2) ^ (d & 7)) << 4) + (jp & 3) * 4);
                *reinterpret_cast<uint32_t*>(smem + SM_VHI + off) = h0 | (h1 << 16);
                *reinterpret_cast<uint32_t*>(smem + SM_VLO + off) = pack_bf2(lo0, lo1);
            }
        }
        __syncthreads();

        // ---- prefetch next tile ----
        if (tt + 1 < HALF_TILES) {
            const char* Kg = (const char*)(K + (size_t)(t + 1) * BN * HDIM);
            const char* Vg = (const char*)(V + (size_t)(t + 1) * BN * HDIM);
#pragma unroll
            for (int it = 0; it < 8; it++) {
                int task = it * THREADS + tid;
                cp16(sb + SM_KRAW + task * 16, Kg + task * 16);
                int r = task >> 5, c = task & 31;
                cp16(sb + SM_VRAW + r * 512 + ((c ^ ((r >> 1) & 7)) << 4), Vg + task * 16);
            }
            CP_COMMIT();
        }

        // ---- S = Q K^T : 16 rows x 64 cols per warp ----
        float sa[8][4];
#pragma unroll
        for (int nb = 0; nb < 8; nb++)
#pragma unroll
            for (int i = 0; i < 4; i++) sa[nb][i] = 0.f;

#pragma unroll
        for (int ks = 0; ks < 8; ks++) {
            uint32_t qh[4], ql[4];
            {
                int r = m0 + l7 + (sub & 1) * 8;
                int ch = ks * 2 + (sub >> 1);
                uint32_t a = sb + SM_QHI + r * 256 + ((ch ^ (r & 7)) << 4);
                ldsm_x4(qh, a);
                ldsm_x4(ql, a + (SM_QLO - SM_QHI));
            }
#pragma unroll
            for (int nbp = 0; nbp < 4; nbp++) {
                uint32_t kh[4], kl[4];
                int r = nbp * 16 + l7 + (sub >> 1) * 8;
                int ch = ks * 2 + (sub & 1);
                uint32_t a = sb + SM_KHI + r * 256 + ((ch ^ (r & 7)) << 4);
                ldsm_x4(kh, a);
                ldsm_x4(kl, a + (SM_KLO - SM_KHI));
                mma_bf16(sa[2 * nbp],     qh, kh);
                mma_bf16(sa[2 * nbp + 1], qh, kh + 2);
                mma_bf16(sa[2 * nbp],     qh, kl);
                mma_bf16(sa[2 * nbp + 1], qh, kl + 2);
                mma_bf16(sa[2 * nbp],     ql, kh);
                mma_bf16(sa[2 * nbp + 1], ql, kh + 2);
            }
        }

        // ---- warp-private online softmax ----
        float rm0 = sa[0][0], rm1 = sa[0][2];
#pragma unroll
        for (int nb = 0; nb < 8; nb++) {
            rm0 = fmaxf(rm0, fmaxf(sa[nb][0], sa[nb][1]));
            rm1 = fmaxf(rm1, fmaxf(sa[nb][2], sa[nb][3]));
        }
        rm0 = fmaxf(rm0, __shfl_xor_sync(0xffffffffu, rm0, 1));
        rm0 = fmaxf(rm0, __shfl_xor_sync(0xffffffffu, rm0, 2));
        rm1 = fmaxf(rm1, __shfl_xor_sync(0xffffffffu, rm1, 1));
        rm1 = fmaxf(rm1, __shfl_xor_sync(0xffffffffu, rm1, 2));

        const float mn0 = fmaxf(mrow[0], rm0);
        const float mn1 = fmaxf(mrow[1], rm1);
        const float al0 = ex2f((mrow[0] - mn0) * LOG2E);
        const float al1 = ex2f((mrow[1] - mn1) * LOG2E);

        float rs0 = 0.f, rs1 = 0.f;
#pragma unroll
        for (int nb = 0; nb < 8; nb++) {
            sa[nb][0] = ex2f((sa[nb][0] - mn0) * LOG2E); rs0 += sa[nb][0];
            sa[nb][1] = ex2f((sa[nb][1] - mn0) * LOG2E); rs0 += sa[nb][1];
            sa[nb][2] = ex2f((sa[nb][2] - mn1) * LOG2E); rs1 += sa[nb][2];
            sa[nb][3] = ex2f((sa[nb][3] - mn1) * LOG2E); rs1 += sa[nb][3];
        }
        rs0 += __shfl_xor_sync(0xffffffffu, rs0, 1);
        rs0 += __shfl_xor_sync(0xffffffffu, rs0, 2);
        rs1 += __shfl_xor_sync(0xffffffffu, rs1, 1);
        rs1 += __shfl_xor_sync(0xffffffffu, rs1, 2);
        lrow[0] = lrow[0] * al0 + rs0;  mrow[0] = mn0;
        lrow[1] = lrow[1] * al1 + rs1;  mrow[1] = mn1;

#pragma unroll
        for (int nb = 0; nb < 16; nb++) {
            oa[nb][0] *= al0; oa[nb][1] *= al0;
            oa[nb][2] *= al1; oa[nb][3] *= al1;
        }

        // ---- O += P V over all 64 j ----
#pragma unroll
        for (int ks = 0; ks < 4; ks++) {
            uint32_t ph[4], pl[4];
#pragma unroll
            for (int h = 0; h < 2; h++) {
                float p0 = sa[2 * ks + h][0], p1 = sa[2 * ks + h][1];
                float p2 = sa[2 * ks + h][2], p3 = sa[2 * ks + h][3];
                uint32_t h0, h1, h2, h3; float l0, l1, l2, l3;
                bfsplit(p0, h0, l0); bfsplit(p1, h1, l1);
                bfsplit(p2, h2, l2); bfsplit(p3, h3, l3);
                ph[2 * h]     = h0 | (h1 << 16);
                ph[2 * h + 1] = h2 | (h3 << 16);
                pl[2 * h]     = pack_bf2(l0, l1);
                pl[2 * h + 1] = pack_bf2(l2, l3);
            }
            const int chb = ks * 2 + (sub & 1);
#pragma unroll
            for (int nbp = 0; nbp < 8; nbp++) {
                uint32_t vh[4], vl[4];
                int r = nbp * 16 + l7 + (sub >> 1) * 8;
                uint32_t a = sb + SM_VHI + r * 128 + ((chb ^ (r & 7)) << 4);
                ldsm_x4(vh, a);
                ldsm_x4(vl, a + (SM_VLO - SM_VHI));
                mma_bf16(oa[2 * nbp],     ph, vh);
                mma_bf16(oa[2 * nbp + 1], ph, vh + 2);
                mma_bf16(oa[2 * nbp],     ph, vl);
                mma_bf16(oa[2 * nbp + 1], ph, vl + 2);
                mma_bf16(oa[2 * nbp],     pl, vh);
                mma_bf16(oa[2 * nbp + 1], pl, vh + 2);
            }
        }
    }

    // ---- epilogue: write partial (A, m, l) to scratch ----
    const int r0 = qbase + m0 + (lane >> 2);
    const int r1 = r0 + 8;
    const int cb = (lane & 3) * 2;
    float* A0 = g_A + ((size_t)kvh * N_SEQ + r0) * HDIM;
    float* A1 = g_A + ((size_t)kvh * N_SEQ + r1) * HDIM;
#pragma unroll
    for (int nb = 0; nb < 16; nb++) {
        *reinterpret_cast<float2*>(A0 + nb * 8 + cb) = make_float2(oa[nb][0], oa[nb][1]);
        *reinterpret_cast<float2*>(A1 + nb * 8 + cb) = make_float2(oa[nb][2], oa[nb][3]);
    }
    if ((lane & 3) == 0) {
        g_M[kvh * N_SEQ + r0] = mrow[0];
        g_M[kvh * N_SEQ + r1] = mrow[1];
        g_L[kvh * N_SEQ + r0] = lrow[0];
        g_L[kvh * N_SEQ + r1] = lrow[1];
    }
}

// ---- merge the two KV halves ----
__global__ __launch_bounds__(256, 4)
void fa_merge_kernel(float* __restrict__ O) {
    int idx = blockIdx.x * blockDim.x + threadIdx.x;   // 8192*16
    int row = idx >> 4;
    int c8  = (idx & 15) * 8;
    float mA = g_M[row], mB = g_M[N_SEQ + row];
    float M = fmaxf(mA, mB);
    float wA = ex2f((mA - M) * LOG2E);
    float wB = ex2f((mB - M) * LOG2E);
    float l = wA * g_L[row] + wB * g_L[N_SEQ + row];
    float inv = 1.0f / l;
    const float* pA = g_A + (size_t)row * HDIM + c8;
    const float* pB = g_A + (size_t)(N_SEQ + row) * HDIM + c8;
    float* pO = O + (size_t)row * HDIM + c8;
#pragma unroll
    for (int h = 0; h < 2; h++) {
        float4 a = *reinterpret_cast<const float4*>(pA + 4 * h);
        float4 b = *reinterpret_cast<const float4*>(pB + 4 * h);
        float4 o;
        o.x = (a.x * wA + b.x * wB) * inv;
        o.y = (a.y * wA + b.y * wB) * inv;
        o.z = (a.z * wA + b.z * wB) * inv;
        o.w = (a.w * wA + b.w * wB) * inv;
        *reinterpret_cast<float4*>(pO + 4 * h) = o;
    }
}

extern "C" void kernel_launch(void* const* d_in, const int* in_sizes, int n_in,
                              void* d_out, int out_size) {
    const float* q = (const float*)d_in[0];
    const float* k = (const float*)d_in[1];
    const float* v = (const float*)d_in[2];
    float* o = (float*)d_out;
    (void)in_sizes; (void)n_in; (void)out_size;

    cudaFuncSetAttribute(fa_hmma_kernel,
                         cudaFuncAttributeMaxDynamicSharedMemorySize, SMEM_BYTES);
    fa_hmma_kernel<<<(N_SEQ / BM) * 2, THREADS, SMEM_BYTES>>>(q, k, v);
    fa_merge_kernel<<<(N_SEQ * 16) / 256, 256>>>(o);
}

// round 11
// speedup vs baseline: 5.1059x; 1.2030x over previous
#include <cuda_runtime.h>
#include <cuda_bf16.h>
#include <cstdint>
#include <math.h>

#define N_SEQ 8192
#define HDIM  128
#define BM    128
#define BN    64
#define NTILES (N_SEQ / BN)      // 128
#define HALF_TILES (NTILES / 2)  // 64 per KV-half
#define THREADS 256
#define LOG2E 1.4426950408889634f

#define KIMG 16384               // bytes per tile image (hi or lo)

// ---- smem byte offsets ----
#define SM_QHI 0                 // 128 rows x 256B
#define SM_QLO 32768
#define SM_BUF 65536             // two 64KB buffers: [KHI 16K][KLO 16K][VHI 16K][VLO 16K]
#define BUFSZ  65536
#define SMEM_BYTES (SM_BUF + 2 * BUFSZ)   // 196608

// pre-converted K/V tile images (swizzled smem layout, ready for cp.async)
__device__ __align__(16) char g_KHI[NTILES * KIMG];
__device__ __align__(16) char g_KLO[NTILES * KIMG];
__device__ __align__(16) char g_VHI[NTILES * KIMG];
__device__ __align__(16) char g_VLO[NTILES * KIMG];

// split-KV scratch
__device__ float g_A[2 * N_SEQ * HDIM];
__device__ float g_M[2 * N_SEQ];
__device__ float g_L[2 * N_SEQ];

// ---------------- helpers ----------------
__device__ __forceinline__ uint32_t smem_u32(const void* p) {
    uint32_t a;
    asm("{ .reg .u64 t; cvta.to.shared.u64 t, %1; cvt.u32.u64 %0, t; }" : "=r"(a) : "l"(p));
    return a;
}
__device__ __forceinline__ float ex2f(float x) {
    float y; asm("ex2.approx.ftz.f32 %0, %1;" : "=f"(y) : "f"(x)); return y;
}
__device__ __forceinline__ void ldsm_x4(uint32_t* r, uint32_t addr) {
    asm volatile("ldmatrix.sync.aligned.m8n8.x4.shared.b16 {%0,%1,%2,%3}, [%4];"
        : "=r"(r[0]), "=r"(r[1]), "=r"(r[2]), "=r"(r[3]) : "r"(addr));
}
__device__ __forceinline__ void mma_bf16(float* c, const uint32_t* a, const uint32_t* b) {
    asm volatile("mma.sync.aligned.m16n8k16.row.col.f32.bf16.bf16.f32 "
        "{%0,%1,%2,%3}, {%4,%5,%6,%7}, {%8,%9}, {%0,%1,%2,%3};"
        : "+f"(c[0]), "+f"(c[1]), "+f"(c[2]), "+f"(c[3])
        : "r"(a[0]), "r"(a[1]), "r"(a[2]), "r"(a[3]), "r"(b[0]), "r"(b[1]));
}
__device__ __forceinline__ void cp16(uint32_t saddr, const void* g) {
    asm volatile("cp.async.cg.shared.global [%0], [%1], 16;" :: "r"(saddr), "l"(g));
}
#define CP_COMMIT() asm volatile("cp.async.commit_group;" ::: "memory")
#define CP_WAIT0()  asm volatile("cp.async.wait_group 0;" ::: "memory")

__device__ __forceinline__ uint32_t pack_bf2(float a, float b) {
    __nv_bfloat162 t = __floats2bfloat162_rn(a, b);
    return *reinterpret_cast<uint32_t*>(&t);
}
__device__ __forceinline__ void bfsplit(float x, uint32_t& hi16, float& lo) {
    uint32_t u = __float_as_uint(x);
    uint32_t h = (u + 0x7FFFu + ((u >> 16) & 1u)) & 0xFFFF0000u;
    hi16 = h >> 16;
    lo = x - __uint_as_float(h);
}

// ---------------- pre-pass: convert K into swizzled tile images ----------------
__global__ __launch_bounds__(256, 4)
void prep_k_kernel(const float* __restrict__ K) {
    int idx = blockIdx.x * blockDim.x + threadIdx.x;      // NTILES*64*32
    int t = idx >> 11, rem = idx & 2047;
    int r = rem >> 5, c4 = rem & 31;
    float4 v = *reinterpret_cast<const float4*>(K + ((size_t)t * BN + r) * HDIM + c4 * 4);
    uint32_t h0, h1, h2, h3; float l0, l1, l2, l3;
    bfsplit(v.x, h0, l0); bfsplit(v.y, h1, l1);
    bfsplit(v.z, h2, l2); bfsplit(v.w, h3, l3);
    uint2 hi = make_uint2(h0 | (h1 << 16), h2 | (h3 << 16));
    uint2 lo = make_uint2(pack_bf2(l0, l1), pack_bf2(l2, l3));
    uint32_t off = (uint32_t)t * KIMG + r * 256
                 + ((((uint32_t)(c4 >> 1)) ^ (r & 7)) << 4) + (c4 & 1) * 8;
    *reinterpret_cast<uint2*>(g_KHI + off) = hi;
    *reinterpret_cast<uint2*>(g_KLO + off) = lo;
}

// ---------------- pre-pass: convert V (transposed) into tile images ----------------
__global__ __launch_bounds__(256, 4)
void prep_v_kernel(const float* __restrict__ V) {
    int idx = blockIdx.x * blockDim.x + threadIdx.x;      // NTILES*32*32
    int t = idx >> 10, rem = idx & 1023;
    int jp = rem & 31, c4 = rem >> 5;
    const float* p0 = V + ((size_t)t * BN + 2 * jp) * HDIM + c4 * 4;
    float4 a = *reinterpret_cast<const float4*>(p0);
    float4 b = *reinterpret_cast<const float4*>(p0 + HDIM);
    float av[4] = {a.x, a.y, a.z, a.w};
    float bv[4] = {b.x, b.y, b.z, b.w};
#pragma unroll
    for (int u = 0; u < 4; u++) {
        int d = 4 * c4 + u;
        uint32_t h0, h1; float lo0, lo1;
        bfsplit(av[u], h0, lo0);
        bfsplit(bv[u], h1, lo1);
        uint32_t off = (uint32_t)t * KIMG + d * 128
                     + ((((uint32_t)(jp >> 2)) ^ (d & 7)) << 4) + (jp & 3) * 4;
        *reinterpret_cast<uint32_t*>(g_VHI + off) = h0 | (h1 << 16);
        *reinterpret_cast<uint32_t*>(g_VLO + off) = pack_bf2(lo0, lo1);
    }
}

// --------------------------------------------------------------------------
__global__ __launch_bounds__(THREADS, 1)
void fa_hmma_kernel(const float* __restrict__ Q) {
    extern __shared__ char smem[];
    const uint32_t sb = smem_u32(smem);
    const int tid  = threadIdx.x;
    const int lane = tid & 31;
    const int wid  = tid >> 5;        // 0..7, owns q-rows [16w, 16w+16)
    const int m0   = wid * 16;
    const int qb   = blockIdx.x >> 1;
    const int kvh  = blockIdx.x & 1;  // KV half
    const int qbase = qb * BM;
    const int t0   = kvh * HALF_TILES;
    const int l7  = lane & 7;
    const int sub = lane >> 3;

    // ---- prefetch tile t0 into buffer 0 ----
    {
        const size_t tb = (size_t)t0 * KIMG;
#pragma unroll
        for (int it = 0; it < 4; it++) {
            int task = (it * THREADS + tid) * 16;
            cp16(sb + SM_BUF + task,         g_KHI + tb + task);
            cp16(sb + SM_BUF + 16384 + task, g_KLO + tb + task);
            cp16(sb + SM_BUF + 32768 + task, g_VHI + tb + task);
            cp16(sb + SM_BUF + 49152 + task, g_VLO + tb + task);
        }
        CP_COMMIT();
    }

    // ---- convert Q once (128 rows) ----
    {
        const float* Qg = Q + (size_t)qbase * HDIM;
#pragma unroll
        for (int it = 0; it < 16; it++) {
            int task = it * THREADS + tid;
            int r = task >> 5, c4 = task & 31;
            float4 v = *reinterpret_cast<const float4*>(Qg + r * HDIM + c4 * 4);
            uint32_t h0, h1, h2, h3; float l0, l1, l2, l3;
            bfsplit(v.x, h0, l0); bfsplit(v.y, h1, l1);
            bfsplit(v.z, h2, l2); bfsplit(v.w, h3, l3);
            uint2 hi = make_uint2(h0 | (h1 << 16), h2 | (h3 << 16));
            uint2 lo = make_uint2(pack_bf2(l0, l1), pack_bf2(l2, l3));
            uint32_t off = (uint32_t)(r * 256 + (((c4 >> 1) ^ (r & 7)) << 4) + (c4 & 1) * 8);
            *reinterpret_cast<uint2*>(smem + SM_QHI + off) = hi;
            *reinterpret_cast<uint2*>(smem + SM_QLO + off) = lo;
        }
    }

    float oa[16][4];
    float mrow[2] = {-INFINITY, -INFINITY};
    float lrow[2] = {0.f, 0.f};
#pragma unroll
    for (int nb = 0; nb < 16; nb++)
#pragma unroll
        for (int i = 0; i < 4; i++) oa[nb][i] = 0.f;

    for (int tt = 0; tt < HALF_TILES; tt++) {
        const int buf = tt & 1;
        const uint32_t kb = sb + SM_BUF + buf * BUFSZ;          // KHI base
        const uint32_t vb = kb + 32768;                         // VHI base

        CP_WAIT0();
        __syncthreads();

        // ---- prefetch next tile into the other buffer ----
        if (tt + 1 < HALF_TILES) {
            const size_t tb = (size_t)(t0 + tt + 1) * KIMG;
            const uint32_t nb_ = sb + SM_BUF + (buf ^ 1) * BUFSZ;
#pragma unroll
            for (int it = 0; it < 4; it++) {
                int task = (it * THREADS + tid) * 16;
                cp16(nb_ + task,         g_KHI + tb + task);
                cp16(nb_ + 16384 + task, g_KLO + tb + task);
                cp16(nb_ + 32768 + task, g_VHI + tb + task);
                cp16(nb_ + 49152 + task, g_VLO + tb + task);
            }
            CP_COMMIT();
        }

        // ---- S = Q K^T : 16 rows x 64 cols per warp ----
        float sa[8][4];
#pragma unroll
        for (int nb = 0; nb < 8; nb++)
#pragma unroll
            for (int i = 0; i < 4; i++) sa[nb][i] = 0.f;

#pragma unroll
        for (int ks = 0; ks < 8; ks++) {
            uint32_t qh[4], ql[4];
            {
                int r = m0 + l7 + (sub & 1) * 8;
                int ch = ks * 2 + (sub >> 1);
                uint32_t a = sb + SM_QHI + r * 256 + ((ch ^ (r & 7)) << 4);
                ldsm_x4(qh, a);
                ldsm_x4(ql, a + (SM_QLO - SM_QHI));
            }
#pragma unroll
            for (int nbp = 0; nbp < 4; nbp++) {
                uint32_t kh[4], kl[4];
                int r = nbp * 16 + l7 + (sub >> 1) * 8;
                int ch = ks * 2 + (sub & 1);
                uint32_t a = kb + r * 256 + ((ch ^ (r & 7)) << 4);
                ldsm_x4(kh, a);
                ldsm_x4(kl, a + 16384);
                mma_bf16(sa[2 * nbp],     qh, kh);
                mma_bf16(sa[2 * nbp + 1], qh, kh + 2);
                mma_bf16(sa[2 * nbp],     qh, kl);
                mma_bf16(sa[2 * nbp + 1], qh, kl + 2);
                mma_bf16(sa[2 * nbp],     ql, kh);
                mma_bf16(sa[2 * nbp + 1], ql, kh + 2);
            }
        }

        // ---- warp-private online softmax ----
        float rm0 = sa[0][0], rm1 = sa[0][2];
#pragma unroll
        for (int nb = 0; nb < 8; nb++) {
            rm0 = fmaxf(rm0, fmaxf(sa[nb][0], sa[nb][1]));
            rm1 = fmaxf(rm1, fmaxf(sa[nb][2], sa[nb][3]));
        }
        rm0 = fmaxf(rm0, __shfl_xor_sync(0xffffffffu, rm0, 1));
        rm0 = fmaxf(rm0, __shfl_xor_sync(0xffffffffu, rm0, 2));
        rm1 = fmaxf(rm1, __shfl_xor_sync(0xffffffffu, rm1, 1));
        rm1 = fmaxf(rm1, __shfl_xor_sync(0xffffffffu, rm1, 2));

        const float mn0 = fmaxf(mrow[0], rm0);
        const float mn1 = fmaxf(mrow[1], rm1);
        const float al0 = ex2f((mrow[0] - mn0) * LOG2E);
        const float al1 = ex2f((mrow[1] - mn1) * LOG2E);

        float rs0 = 0.f, rs1 = 0.f;
#pragma unroll
        for (int nb = 0; nb < 8; nb++) {
            sa[nb][0] = ex2f((sa[nb][0] - mn0) * LOG2E); rs0 += sa[nb][0];
            sa[nb][1] = ex2f((sa[nb][1] - mn0) * LOG2E); rs0 += sa[nb][1];
            sa[nb][2] = ex2f((sa[nb][2] - mn1) * LOG2E); rs1 += sa[nb][2];
            sa[nb][3] = ex2f((sa[nb][3] - mn1) * LOG2E); rs1 += sa[nb][3];
        }
        rs0 += __shfl_xor_sync(0xffffffffu, rs0, 1);
        rs0 += __shfl_xor_sync(0xffffffffu, rs0, 2);
        rs1 += __shfl_xor_sync(0xffffffffu, rs1, 1);
        rs1 += __shfl_xor_sync(0xffffffffu, rs1, 2);
        lrow[0] = lrow[0] * al0 + rs0;  mrow[0] = mn0;
        lrow[1] = lrow[1] * al1 + rs1;  mrow[1] = mn1;

#pragma unroll
        for (int nb = 0; nb < 16; nb++) {
            oa[nb][0] *= al0; oa[nb][1] *= al0;
            oa[nb][2] *= al1; oa[nb][3] *= al1;
        }

        // ---- O += P V over all 64 j ----
#pragma unroll
        for (int ks = 0; ks < 4; ks++) {
            uint32_t ph[4], pl[4];
#pragma unroll
            for (int h = 0; h < 2; h++) {
                float p0 = sa[2 * ks + h][0], p1 = sa[2 * ks + h][1];
                float p2 = sa[2 * ks + h][2], p3 = sa[2 * ks + h][3];
                uint32_t h0, h1, h2, h3; float l0, l1, l2, l3;
                bfsplit(p0, h0, l0); bfsplit(p1, h1, l1);
                bfsplit(p2, h2, l2); bfsplit(p3, h3, l3);
                ph[2 * h]     = h0 | (h1 << 16);
                ph[2 * h + 1] = h2 | (h3 << 16);
                pl[2 * h]     = pack_bf2(l0, l1);
                pl[2 * h + 1] = pack_bf2(l2, l3);
            }
            const int chb = ks * 2 + (sub & 1);
#pragma unroll
            for (int nbp = 0; nbp < 8; nbp++) {
                uint32_t vh[4], vl[4];
                int r = nbp * 16 + l7 + (sub >> 1) * 8;
                uint32_t a = vb + r * 128 + ((chb ^ (r & 7)) << 4);
                ldsm_x4(vh, a);
                ldsm_x4(vl, a + 16384);
                mma_bf16(oa[2 * nbp],     ph, vh);
                mma_bf16(oa[2 * nbp + 1], ph, vh + 2);
                mma_bf16(oa[2 * nbp],     ph, vl);
                mma_bf16(oa[2 * nbp + 1], ph, vl + 2);
                mma_bf16(oa[2 * nbp],     pl, vh);
                mma_bf16(oa[2 * nbp + 1], pl, vh + 2);
            }
        }
    }

    // ---- epilogue: write partial (A, m, l) to scratch ----
    const int r0 = qbase + m0 + (lane >> 2);
    const int r1 = r0 + 8;
    const int cb = (lane & 3) * 2;
    float* A0 = g_A + ((size_t)kvh * N_SEQ + r0) * HDIM;
    float* A1 = g_A + ((size_t)kvh * N_SEQ + r1) * HDIM;
#pragma unroll
    for (int nb = 0; nb < 16; nb++) {
        *reinterpret_cast<float2*>(A0 + nb * 8 + cb) = make_float2(oa[nb][0], oa[nb][1]);
        *reinterpret_cast<float2*>(A1 + nb * 8 + cb) = make_float2(oa[nb][2], oa[nb][3]);
    }
    if ((lane & 3) == 0) {
        g_M[kvh * N_SEQ + r0] = mrow[0];
        g_M[kvh * N_SEQ + r1] = mrow[1];
        g_L[kvh * N_SEQ + r0] = lrow[0];
        g_L[kvh * N_SEQ + r1] = lrow[1];
    }
}

// ---- merge the two KV halves ----
__global__ __launch_bounds__(256, 4)
void fa_merge_kernel(float* __restrict__ O) {
    int idx = blockIdx.x * blockDim.x + threadIdx.x;   // 8192*16
    int row = idx >> 4;
    int c8  = (idx & 15) * 8;
    float mA = g_M[row], mB = g_M[N_SEQ + row];
    float M = fmaxf(mA, mB);
    float wA = ex2f((mA - M) * LOG2E);
    float wB = ex2f((mB - M) * LOG2E);
    float l = wA * g_L[row] + wB * g_L[N_SEQ + row];
    float inv = 1.0f / l;
    const float* pA = g_A + (size_t)row * HDIM + c8;
    const float* pB = g_A + (size_t)(N_SEQ + row) * HDIM + c8;
    float* pO = O + (size_t)row * HDIM + c8;
#pragma unroll
    for (int h = 0; h < 2; h++) {
        float4 a = *reinterpret_cast<const float4*>(pA + 4 * h);
        float4 b = *reinterpret_cast<const float4*>(pB + 4 * h);
        float4 o;
        o.x = (a.x * wA + b.x * wB) * inv;
        o.y = (a.y * wA + b.y * wB) * inv;
        o.z = (a.z * wA + b.z * wB) * inv;
        o.w = (a.w * wA + b.w * wB) * inv;
        *reinterpret_cast<float4*>(pO + 4 * h) = o;
    }
}

extern "C" void kernel_launch(void* const* d_in, const int* in_sizes, int n_in,
                              void* d_out, int out_size) {
    const float* q = (const float*)d_in[0];
    const float* k = (const float*)d_in[1];
    const float* v = (const float*)d_in[2];
    float* o = (float*)d_out;
    (void)in_sizes; (void)n_in; (void)out_size;

    prep_k_kernel<<<(NTILES * 64 * 32) / 256, 256>>>(k);
    prep_v_kernel<<<(NTILES * 32 * 32) / 256, 256>>>(v);

    cudaFuncSetAttribute(fa_hmma_kernel,
                         cudaFuncAttributeMaxDynamicSharedMemorySize, SMEM_BYTES);
    fa_hmma_kernel<<<(N_SEQ / BM) * 2, THREADS, SMEM_BYTES>>>(q);
    fa_merge_kernel<<<(N_SEQ * 16) / 256, 256>>>(o);
}

// round 12
// speedup vs baseline: 6.3049x; 1.2348x over previous
#include <cuda_runtime.h>
#include <cuda_fp16.h>
#include <cstdint>
#include <math.h>

#define N_SEQ 8192
#define HDIM  128
#define BM    128
#define BN    64
#define NTILES (N_SEQ / BN)      // 128
#define HALF_TILES (NTILES / 2)  // 64 per KV-half
#define THREADS 256
#define LOG2E 1.4426950408889634f

#define KIMG 16384               // bytes per tile image (hi or lo)

// ---- smem byte offsets ----
// two 64KB KV buffers: [KHI 16K][KLO 16K][VHI 16K][VLO 16K]; buffer1 doubles
// as the Q-image staging area before the mainloop starts.
#define SM_BUF 0
#define BUFSZ  65536
#define SMEM_BYTES (2 * BUFSZ)   // 131072

// pre-converted K/V tile images (swizzled smem layout, ready for cp.async)
__device__ __align__(16) char g_KHI[NTILES * KIMG];
__device__ __align__(16) char g_KLO[NTILES * KIMG];
__device__ __align__(16) char g_VHI[NTILES * KIMG];
__device__ __align__(16) char g_VLO[NTILES * KIMG];

// split-KV scratch
__device__ float g_A[2 * N_SEQ * HDIM];
__device__ float g_M[2 * N_SEQ];
__device__ float g_L[2 * N_SEQ];

// ---------------- helpers ----------------
__device__ __forceinline__ uint32_t smem_u32(const void* p) {
    uint32_t a;
    asm("{ .reg .u64 t; cvta.to.shared.u64 t, %1; cvt.u32.u64 %0, t; }" : "=r"(a) : "l"(p));
    return a;
}
__device__ __forceinline__ float ex2f(float x) {
    float y; asm("ex2.approx.ftz.f32 %0, %1;" : "=f"(y) : "f"(x)); return y;
}
__device__ __forceinline__ void ldsm_x4(uint32_t* r, uint32_t addr) {
    asm volatile("ldmatrix.sync.aligned.m8n8.x4.shared.b16 {%0,%1,%2,%3}, [%4];"
        : "=r"(r[0]), "=r"(r[1]), "=r"(r[2]), "=r"(r[3]) : "r"(addr));
}
__device__ __forceinline__ void mma_f16(float* c, const uint32_t* a, const uint32_t* b) {
    asm volatile("mma.sync.aligned.m16n8k16.row.col.f32.f16.f16.f32 "
        "{%0,%1,%2,%3}, {%4,%5,%6,%7}, {%8,%9}, {%0,%1,%2,%3};"
        : "+f"(c[0]), "+f"(c[1]), "+f"(c[2]), "+f"(c[3])
        : "r"(a[0]), "r"(a[1]), "r"(a[2]), "r"(a[3]), "r"(b[0]), "r"(b[1]));
}
__device__ __forceinline__ void cp16(uint32_t saddr, const void* g) {
    asm volatile("cp.async.cg.shared.global [%0], [%1], 16;" :: "r"(saddr), "l"(g));
}
#define CP_COMMIT() asm volatile("cp.async.commit_group;" ::: "memory")
#define CP_WAIT0()  asm volatile("cp.async.wait_group 0;" ::: "memory")

__device__ __forceinline__ uint32_t pack_h2(float a, float b) {
    __half2 t = __floats2half2_rn(a, b);
    return *reinterpret_cast<uint32_t*>(&t);
}
// split x into fp16-hi (rn, low-16 bits) and fp32 residual
__device__ __forceinline__ void hsplit(float x, uint32_t& hi16, float& lo) {
    __half h = __float2half_rn(x);
    hi16 = (uint32_t)*reinterpret_cast<uint16_t*>(&h);
    lo = x - __half2float(h);
}

// ---------------- pre-pass: convert K into swizzled tile images ----------------
__global__ __launch_bounds__(256, 4)
void prep_k_kernel(const float* __restrict__ K) {
    int idx = blockIdx.x * blockDim.x + threadIdx.x;      // NTILES*64*32
    int t = idx >> 11, rem = idx & 2047;
    int r = rem >> 5, c4 = rem & 31;
    float4 v = *reinterpret_cast<const float4*>(K + ((size_t)t * BN + r) * HDIM + c4 * 4);
    uint32_t h0, h1, h2, h3; float l0, l1, l2, l3;
    hsplit(v.x, h0, l0); hsplit(v.y, h1, l1);
    hsplit(v.z, h2, l2); hsplit(v.w, h3, l3);
    uint2 hi = make_uint2(h0 | (h1 << 16), h2 | (h3 << 16));
    uint2 lo = make_uint2(pack_h2(l0, l1), pack_h2(l2, l3));
    uint32_t off = (uint32_t)t * KIMG + r * 256
                 + ((((uint32_t)(c4 >> 1)) ^ (r & 7)) << 4) + (c4 & 1) * 8;
    *reinterpret_cast<uint2*>(g_KHI + off) = hi;
    *reinterpret_cast<uint2*>(g_KLO + off) = lo;
}

// ---------------- pre-pass: convert V (transposed) into tile images ----------------
__global__ __launch_bounds__(256, 4)
void prep_v_kernel(const float* __restrict__ V) {
    int idx = blockIdx.x * blockDim.x + threadIdx.x;      // NTILES*32*32
    int t = idx >> 10, rem = idx & 1023;
    int jp = rem & 31, c4 = rem >> 5;
    const float* p0 = V + ((size_t)t * BN + 2 * jp) * HDIM + c4 * 4;
    float4 a = *reinterpret_cast<const float4*>(p0);
    float4 b = *reinterpret_cast<const float4*>(p0 + HDIM);
    float av[4] = {a.x, a.y, a.z, a.w};
    float bv[4] = {b.x, b.y, b.z, b.w};
#pragma unroll
    for (int u = 0; u < 4; u++) {
        int d = 4 * c4 + u;
        uint32_t h0, h1; float lo0, lo1;
        hsplit(av[u], h0, lo0);
        hsplit(bv[u], h1, lo1);
        uint32_t off = (uint32_t)t * KIMG + d * 128
                     + ((((uint32_t)(jp >> 2)) ^ (d & 7)) << 4) + (jp & 3) * 4;
        *reinterpret_cast<uint32_t*>(g_VHI + off) = h0 | (h1 << 16);
        *reinterpret_cast<uint32_t*>(g_VLO + off) = pack_h2(lo0, lo1);
    }
}

// --------------------------------------------------------------------------
__global__ __launch_bounds__(THREADS, 1)
void fa_hmma_kernel(const float* __restrict__ Q) {
    extern __shared__ char smem[];
    const uint32_t sb = smem_u32(smem);
    const int tid  = threadIdx.x;
    const int lane = tid & 31;
    const int wid  = tid >> 5;        // 0..7, owns q-rows [16w, 16w+16)
    const int m0   = wid * 16;
    const int qb   = blockIdx.x >> 1;
    const int kvh  = blockIdx.x & 1;  // KV half
    const int qbase = qb * BM;
    const int t0   = kvh * HALF_TILES;
    const int l7  = lane & 7;
    const int sub = lane >> 3;

    // ---- prefetch tile t0 into buffer 0 ----
    {
        const size_t tb = (size_t)t0 * KIMG;
#pragma unroll
        for (int it = 0; it < 4; it++) {
            int task = (it * THREADS + tid) * 16;
            cp16(sb + SM_BUF + task,         g_KHI + tb + task);
            cp16(sb + SM_BUF + 16384 + task, g_KLO + tb + task);
            cp16(sb + SM_BUF + 32768 + task, g_VHI + tb + task);
            cp16(sb + SM_BUF + 49152 + task, g_VLO + tb + task);
        }
        CP_COMMIT();
    }

    // ---- convert Q into staging image (buffer 1), then load frags to regs ----
    {
        const float* Qg = Q + (size_t)qbase * HDIM;
#pragma unroll
        for (int it = 0; it < 16; it++) {
            int task = it * THREADS + tid;
            int r = task >> 5, c4 = task & 31;
            float4 v = *reinterpret_cast<const float4*>(Qg + r * HDIM + c4 * 4);
            uint32_t h0, h1, h2, h3; float l0, l1, l2, l3;
            hsplit(v.x, h0, l0); hsplit(v.y, h1, l1);
            hsplit(v.z, h2, l2); hsplit(v.w, h3, l3);
            uint2 hi = make_uint2(h0 | (h1 << 16), h2 | (h3 << 16));
            uint2 lo = make_uint2(pack_h2(l0, l1), pack_h2(l2, l3));
            uint32_t off = (uint32_t)(r * 256 + (((c4 >> 1) ^ (r & 7)) << 4) + (c4 & 1) * 8);
            *reinterpret_cast<uint2*>(smem + SM_BUF + BUFSZ + off) = hi;        // QHI image
            *reinterpret_cast<uint2*>(smem + SM_BUF + BUFSZ + 32768 + off) = lo; // QLO image
        }
    }
    __syncthreads();

    uint32_t qfh[8][4], qfl[8][4];
    {
        int r = m0 + l7 + (sub & 1) * 8;
#pragma unroll
        for (int ks = 0; ks < 8; ks++) {
            int ch = ks * 2 + (sub >> 1);
            uint32_t a = sb + SM_BUF + BUFSZ + r * 256 + ((ch ^ (r & 7)) << 4);
            ldsm_x4(qfh[ks], a);
            ldsm_x4(qfl[ks], a + 32768);
        }
    }

    float oa[16][4];
    float mrow[2] = {-INFINITY, -INFINITY};
    float lrow[2] = {0.f, 0.f};
#pragma unroll
    for (int nb = 0; nb < 16; nb++)
#pragma unroll
        for (int i = 0; i < 4; i++) oa[nb][i] = 0.f;

    for (int tt = 0; tt < HALF_TILES; tt++) {
        const int buf = tt & 1;
        const uint32_t kb = sb + SM_BUF + buf * BUFSZ;          // KHI base
        const uint32_t vb = kb + 32768;                         // VHI base

        CP_WAIT0();
        __syncthreads();

        // ---- prefetch next tile into the other buffer ----
        if (tt + 1 < HALF_TILES) {
            const size_t tb = (size_t)(t0 + tt + 1) * KIMG;
            const uint32_t nb_ = sb + SM_BUF + (buf ^ 1) * BUFSZ;
#pragma unroll
            for (int it = 0; it < 4; it++) {
                int task = (it * THREADS + tid) * 16;
                cp16(nb_ + task,         g_KHI + tb + task);
                cp16(nb_ + 16384 + task, g_KLO + tb + task);
                cp16(nb_ + 32768 + task, g_VHI + tb + task);
                cp16(nb_ + 49152 + task, g_VLO + tb + task);
            }
            CP_COMMIT();
        }

        // ---- S = Q K^T : 16 rows x 64 cols per warp (3-term fp16 split) ----
        float sa[8][4];
#pragma unroll
        for (int nb = 0; nb < 8; nb++)
#pragma unroll
            for (int i = 0; i < 4; i++) sa[nb][i] = 0.f;

#pragma unroll
        for (int ks = 0; ks < 8; ks++) {
#pragma unroll
            for (int nbp = 0; nbp < 4; nbp++) {
                uint32_t kh[4], kl[4];
                int r = nbp * 16 + l7 + (sub >> 1) * 8;
                int ch = ks * 2 + (sub & 1);
                uint32_t a = kb + r * 256 + ((ch ^ (r & 7)) << 4);
                ldsm_x4(kh, a);
                ldsm_x4(kl, a + 16384);
                mma_f16(sa[2 * nbp],     qfh[ks], kh);
                mma_f16(sa[2 * nbp + 1], qfh[ks], kh + 2);
                mma_f16(sa[2 * nbp],     qfh[ks], kl);
                mma_f16(sa[2 * nbp + 1], qfh[ks], kl + 2);
                mma_f16(sa[2 * nbp],     qfl[ks], kh);
                mma_f16(sa[2 * nbp + 1], qfl[ks], kh + 2);
            }
        }

        // ---- warp-private online softmax ----
        float rm0 = sa[0][0], rm1 = sa[0][2];
#pragma unroll
        for (int nb = 0; nb < 8; nb++) {
            rm0 = fmaxf(rm0, fmaxf(sa[nb][0], sa[nb][1]));
            rm1 = fmaxf(rm1, fmaxf(sa[nb][2], sa[nb][3]));
        }
        rm0 = fmaxf(rm0, __shfl_xor_sync(0xffffffffu, rm0, 1));
        rm0 = fmaxf(rm0, __shfl_xor_sync(0xffffffffu, rm0, 2));
        rm1 = fmaxf(rm1, __shfl_xor_sync(0xffffffffu, rm1, 1));
        rm1 = fmaxf(rm1, __shfl_xor_sync(0xffffffffu, rm1, 2));

        const float mn0 = fmaxf(mrow[0], rm0);
        const float mn1 = fmaxf(mrow[1], rm1);
        const float al0 = ex2f((mrow[0] - mn0) * LOG2E);
        const float al1 = ex2f((mrow[1] - mn1) * LOG2E);

        float rs0 = 0.f, rs1 = 0.f;
#pragma unroll
        for (int nb = 0; nb < 8; nb++) {
            sa[nb][0] = ex2f((sa[nb][0] - mn0) * LOG2E); rs0 += sa[nb][0];
            sa[nb][1] = ex2f((sa[nb][1] - mn0) * LOG2E); rs0 += sa[nb][1];
            sa[nb][2] = ex2f((sa[nb][2] - mn1) * LOG2E); rs1 += sa[nb][2];
            sa[nb][3] = ex2f((sa[nb][3] - mn1) * LOG2E); rs1 += sa[nb][3];
        }
        rs0 += __shfl_xor_sync(0xffffffffu, rs0, 1);
        rs0 += __shfl_xor_sync(0xffffffffu, rs0, 2);
        rs1 += __shfl_xor_sync(0xffffffffu, rs1, 1);
        rs1 += __shfl_xor_sync(0xffffffffu, rs1, 2);
        lrow[0] = lrow[0] * al0 + rs0;  mrow[0] = mn0;
        lrow[1] = lrow[1] * al1 + rs1;  mrow[1] = mn1;

#pragma unroll
        for (int nb = 0; nb < 16; nb++) {
            oa[nb][0] *= al0; oa[nb][1] *= al0;
            oa[nb][2] *= al1; oa[nb][3] *= al1;
        }

        // ---- O += P V (2-term fp16: ph*vh + ph*vl) ----
#pragma unroll
        for (int ks = 0; ks < 4; ks++) {
            uint32_t ph[4];
#pragma unroll
            for (int h = 0; h < 2; h++) {
                ph[2 * h]     = pack_h2(sa[2 * ks + h][0], sa[2 * ks + h][1]);
                ph[2 * h + 1] = pack_h2(sa[2 * ks + h][2], sa[2 * ks + h][3]);
            }
            const int chb = ks * 2 + (sub & 1);
#pragma unroll
            for (int nbp = 0; nbp < 8; nbp++) {
                uint32_t vh[4], vl[4];
                int r = nbp * 16 + l7 + (sub >> 1) * 8;
                uint32_t a = vb + r * 128 + ((chb ^ (r & 7)) << 4);
                ldsm_x4(vh, a);
                ldsm_x4(vl, a + 16384);
                mma_f16(oa[2 * nbp],     ph, vh);
                mma_f16(oa[2 * nbp + 1], ph, vh + 2);
                mma_f16(oa[2 * nbp],     ph, vl);
                mma_f16(oa[2 * nbp + 1], ph, vl + 2);
            }
        }
    }

    // ---- epilogue: write partial (A, m, l) to scratch ----
    const int r0 = qbase + m0 + (lane >> 2);
    const int r1 = r0 + 8;
    const int cb = (lane & 3) * 2;
    float* A0 = g_A + ((size_t)kvh * N_SEQ + r0) * HDIM;
    float* A1 = g_A + ((size_t)kvh * N_SEQ + r1) * HDIM;
#pragma unroll
    for (int nb = 0; nb < 16; nb++) {
        *reinterpret_cast<float2*>(A0 + nb * 8 + cb) = make_float2(oa[nb][0], oa[nb][1]);
        *reinterpret_cast<float2*>(A1 + nb * 8 + cb) = make_float2(oa[nb][2], oa[nb][3]);
    }
    if ((lane & 3) == 0) {
        g_M[kvh * N_SEQ + r0] = mrow[0];
        g_M[kvh * N_SEQ + r1] = mrow[1];
        g_L[kvh * N_SEQ + r0] = lrow[0];
        g_L[kvh * N_SEQ + r1] = lrow[1];
    }
}

// ---- merge the two KV halves ----
__global__ __launch_bounds__(256, 4)
void fa_merge_kernel(float* __restrict__ O) {
    int idx = blockIdx.x * blockDim.x + threadIdx.x;   // 8192*16
    int row = idx >> 4;
    int c8  = (idx & 15) * 8;
    float mA = g_M[row], mB = g_M[N_SEQ + row];
    float M = fmaxf(mA, mB);
    float wA = ex2f((mA - M) * LOG2E);
    float wB = ex2f((mB - M) * LOG2E);
    float l = wA * g_L[row] + wB * g_L[N_SEQ + row];
    float inv = 1.0f / l;
    const float* pA = g_A + (size_t)row * HDIM + c8;
    const float* pB = g_A + (size_t)(N_SEQ + row) * HDIM + c8;
    float* pO = O + (size_t)row * HDIM + c8;
#pragma unroll
    for (int h = 0; h < 2; h++) {
        float4 a = *reinterpret_cast<const float4*>(pA + 4 * h);
        float4 b = *reinterpret_cast<const float4*>(pB + 4 * h);
        float4 o;
        o.x = (a.x * wA + b.x * wB) * inv;
        o.y = (a.y * wA + b.y * wB) * inv;
        o.z = (a.z * wA + b.z * wB) * inv;
        o.w = (a.w * wA + b.w * wB) * inv;
        *reinterpret_cast<float4*>(pO + 4 * h) = o;
    }
}

extern "C" void kernel_launch(void* const* d_in, const int* in_sizes, int n_in,
                              void* d_out, int out_size) {
    const float* q = (const float*)d_in[0];
    const float* k = (const float*)d_in[1];
    const float* v = (const float*)d_in[2];
    float* o = (float*)d_out;
    (void)in_sizes; (void)n_in; (void)out_size;

    prep_k_kernel<<<(NTILES * 64 * 32) / 256, 256>>>(k);
    prep_v_kernel<<<(NTILES * 32 * 32) / 256, 256>>>(v);

    cudaFuncSetAttribute(fa_hmma_kernel,
                         cudaFuncAttributeMaxDynamicSharedMemorySize, SMEM_BYTES);
    fa_hmma_kernel<<<(N_SEQ / BM) * 2, THREADS, SMEM_BYTES>>>(q);
    fa_merge_kernel<<<(N_SEQ * 16) / 256, 256>>>(o);
}

// round 14
// speedup vs baseline: 7.5539x; 1.1981x over previous
#include <cuda_runtime.h>
#include <cuda_fp16.h>
#include <cstdint>
#include <math.h>

#define N_SEQ 8192
#define HDIM  128
#define BM    128
#define BN    64
#define NTILES (N_SEQ / BN)      // 128
#define HALF_TILES (NTILES / 2)  // 64 per KV-half
#define THREADS 256
#define LOG2E 1.4426950408889634f

#define KIMG 16384               // bytes per tile image (hi or lo)

// ---- smem ----
// two 48KB KV buffers: [KHI 16K][KLO 16K][VHI 16K]
// Q-image (64KB) staged over the whole region before the mainloop.
#define BUFSZ  49152
#define SMEM_BYTES (2 * BUFSZ)   // 98304

// pre-converted K/V tile images (swizzled smem layout, ready for cp.async)
__device__ __align__(16) char g_KHI[NTILES * KIMG];
__device__ __align__(16) char g_KLO[NTILES * KIMG];
__device__ __align__(16) char g_VHI[NTILES * KIMG];

// split-KV scratch
__device__ float g_A[2 * N_SEQ * HDIM];
__device__ float g_M[2 * N_SEQ];
__device__ float g_L[2 * N_SEQ];

// ---------------- helpers ----------------
__device__ __forceinline__ uint32_t smem_u32(const void* p) {
    uint32_t a;
    asm("{ .reg .u64 t; cvta.to.shared.u64 t, %1; cvt.u32.u64 %0, t; }" : "=r"(a) : "l"(p));
    return a;
}
__device__ __forceinline__ float ex2f(float x) {
    float y; asm("ex2.approx.ftz.f32 %0, %1;" : "=f"(y) : "f"(x)); return y;
}
__device__ __forceinline__ void ldsm_x4(uint32_t* r, uint32_t addr) {
    asm volatile("ldmatrix.sync.aligned.m8n8.x4.shared.b16 {%0,%1,%2,%3}, [%4];"
        : "=r"(r[0]), "=r"(r[1]), "=r"(r[2]), "=r"(r[3]) : "r"(addr));
}
__device__ __forceinline__ void mma_f16(float* c, const uint32_t* a, const uint32_t* b) {
    asm volatile("mma.sync.aligned.m16n8k16.row.col.f32.f16.f16.f32 "
        "{%0,%1,%2,%3}, {%4,%5,%6,%7}, {%8,%9}, {%0,%1,%2,%3};"
        : "+f"(c[0]), "+f"(c[1]), "+f"(c[2]), "+f"(c[3])
        : "r"(a[0]), "r"(a[1]), "r"(a[2]), "r"(a[3]), "r"(b[0]), "r"(b[1]));
}
__device__ __forceinline__ void cp16(uint32_t saddr, const void* g) {
    asm volatile("cp.async.cg.shared.global [%0], [%1], 16;" :: "r"(saddr), "l"(g));
}
#define CP_COMMIT() asm volatile("cp.async.commit_group;" ::: "memory")
#define CP_WAIT0()  asm volatile("cp.async.wait_group 0;" ::: "memory")

__device__ __forceinline__ uint32_t pack_h2(float a, float b) {
    __half2 t = __floats2half2_rn(a, b);
    return *reinterpret_cast<uint32_t*>(&t);
}
__device__ __forceinline__ void hsplit(float x, uint32_t& hi16, float& lo) {
    __half h = __float2half_rn(x);
    hi16 = (uint32_t)*reinterpret_cast<uint16_t*>(&h);
    lo = x - __half2float(h);
}

// ---------------- pre-pass: K -> swizzled hi/lo tile images ----------------
__global__ __launch_bounds__(256, 4)
void prep_k_kernel(const float* __restrict__ K) {
    int idx = blockIdx.x * blockDim.x + threadIdx.x;      // NTILES*64*32
    int t = idx >> 11, rem = idx & 2047;
    int r = rem >> 5, c4 = rem & 31;
    float4 v = *reinterpret_cast<const float4*>(K + ((size_t)t * BN + r) * HDIM + c4 * 4);
    uint32_t h0, h1, h2, h3; float l0, l1, l2, l3;
    hsplit(v.x, h0, l0); hsplit(v.y, h1, l1);
    hsplit(v.z, h2, l2); hsplit(v.w, h3, l3);
    uint2 hi = make_uint2(h0 | (h1 << 16), h2 | (h3 << 16));
    uint2 lo = make_uint2(pack_h2(l0, l1), pack_h2(l2, l3));
    uint32_t off = (uint32_t)t * KIMG + r * 256
                 + ((((uint32_t)(c4 >> 1)) ^ (r & 7)) << 4) + (c4 & 1) * 8;
    *reinterpret_cast<uint2*>(g_KHI + off) = hi;
    *reinterpret_cast<uint2*>(g_KLO + off) = lo;
}

// ---------------- pre-pass: V (transposed, fp16 only) ----------------
__global__ __launch_bounds__(256, 4)
void prep_v_kernel(const float* __restrict__ V) {
    int idx = blockIdx.x * blockDim.x + threadIdx.x;      // NTILES*32*32
    int t = idx >> 10, rem = idx & 1023;
    int jp = rem & 31, c4 = rem >> 5;
    const float* p0 = V + ((size_t)t * BN + 2 * jp) * HDIM + c4 * 4;
    float4 a = *reinterpret_cast<const float4*>(p0);
    float4 b = *reinterpret_cast<const float4*>(p0 + HDIM);
    float av[4] = {a.x, a.y, a.z, a.w};
    float bv[4] = {b.x, b.y, b.z, b.w};
#pragma unroll
    for (int u = 0; u < 4; u++) {
        int d = 4 * c4 + u;
        uint32_t off = (uint32_t)t * KIMG + d * 128
                     + ((((uint32_t)(jp >> 2)) ^ (d & 7)) << 4) + (jp & 3) * 4;
        *reinterpret_cast<uint32_t*>(g_VHI + off) = pack_h2(av[u], bv[u]);
    }
}

// --------------------------------------------------------------------------
__global__ __launch_bounds__(THREADS, 1)
void fa_hmma_kernel(const float* __restrict__ Q) {
    extern __shared__ char smem[];
    const uint32_t sb = smem_u32(smem);
    const int tid  = threadIdx.x;
    const int lane = tid & 31;
    const int wid  = tid >> 5;        // 0..7, owns q-rows [16w, 16w+16)
    const int m0   = wid * 16;
    const int qb   = blockIdx.x >> 1;
    const int kvh  = blockIdx.x & 1;  // KV half
    const int qbase = qb * BM;
    const int t0   = kvh * HALF_TILES;
    const int l7  = lane & 7;
    const int sub = lane >> 3;

    // ---- convert Q into staging image at smem[0,64K), load frags, release ----
    {
        const float* Qg = Q + (size_t)qbase * HDIM;
#pragma unroll
        for (int it = 0; it < 16; it++) {
            int task = it * THREADS + tid;
            int r = task >> 5, c4 = task & 31;
            float4 v = *reinterpret_cast<const float4*>(Qg + r * HDIM + c4 * 4);
            uint32_t h0, h1, h2, h3; float l0, l1, l2, l3;
            hsplit(v.x, h0, l0); hsplit(v.y, h1, l1);
            hsplit(v.z, h2, l2); hsplit(v.w, h3, l3);
            uint2 hi = make_uint2(h0 | (h1 << 16), h2 | (h3 << 16));
            uint2 lo = make_uint2(pack_h2(l0, l1), pack_h2(l2, l3));
            uint32_t off = (uint32_t)(r * 256 + (((c4 >> 1) ^ (r & 7)) << 4) + (c4 & 1) * 8);
            *reinterpret_cast<uint2*>(smem + off) = hi;           // QHI image
            *reinterpret_cast<uint2*>(smem + 32768 + off) = lo;   // QLO image
        }
    }
    __syncthreads();

    uint32_t qfh[8][4], qfl[8][4];
    {
        int r = m0 + l7 + (sub & 1) * 8;
#pragma unroll
        for (int ks = 0; ks < 8; ks++) {
            int ch = ks * 2 + (sub >> 1);
            uint32_t a = sb + r * 256 + ((ch ^ (r & 7)) << 4);
            ldsm_x4(qfh[ks], a);
            ldsm_x4(qfl[ks], a + 32768);
        }
    }
    __syncthreads();   // everyone done reading Q before buffers are reused

    // ---- prefetch tile t0 into buffer 0 ----
    {
        const size_t tb = (size_t)t0 * KIMG;
#pragma unroll
        for (int it = 0; it < 4; it++) {
            int task = (it * THREADS + tid) * 16;
            cp16(sb + task,         g_KHI + tb + task);
            cp16(sb + 16384 + task, g_KLO + tb + task);
            cp16(sb + 32768 + task, g_VHI + tb + task);
        }
        CP_COMMIT();
    }

    float oa[16][4];
    float mrow[2] = {-INFINITY, -INFINITY};
    float lrow[2] = {0.f, 0.f};
#pragma unroll
    for (int nb = 0; nb < 16; nb++)
#pragma unroll
        for (int i = 0; i < 4; i++) oa[nb][i] = 0.f;

    for (int tt = 0; tt < HALF_TILES; tt++) {
        const int buf = tt & 1;
        const uint32_t kb = sb + buf * BUFSZ;           // KHI base
        const uint32_t vb = kb + 32768;                 // VHI base

        CP_WAIT0();
        __syncthreads();

        // ---- prefetch next tile into the other buffer ----
        if (tt + 1 < HALF_TILES) {
            const size_t tb = (size_t)(t0 + tt + 1) * KIMG;
            const uint32_t nb_ = sb + (buf ^ 1) * BUFSZ;
#pragma unroll
            for (int it = 0; it < 4; it++) {
                int task = (it * THREADS + tid) * 16;
                cp16(nb_ + task,         g_KHI + tb + task);
                cp16(nb_ + 16384 + task, g_KLO + tb + task);
                cp16(nb_ + 32768 + task, g_VHI + tb + task);
            }
            CP_COMMIT();
        }

        // ---- S = Q K^T : 3-term fp16 split ----
        float sa[8][4];
#pragma unroll
        for (int nb = 0; nb < 8; nb++)
#pragma unroll
            for (int i = 0; i < 4; i++) sa[nb][i] = 0.f;

#pragma unroll
        for (int ks = 0; ks < 8; ks++) {
#pragma unroll
            for (int nbp = 0; nbp < 4; nbp++) {
                uint32_t kh[4], kl[4];
                int r = nbp * 16 + l7 + (sub >> 1) * 8;
                int ch = ks * 2 + (sub & 1);
                uint32_t a = kb + r * 256 + ((ch ^ (r & 7)) << 4);
                ldsm_x4(kh, a);
                ldsm_x4(kl, a + 16384);
                mma_f16(sa[2 * nbp],     qfh[ks], kh);
                mma_f16(sa[2 * nbp + 1], qfh[ks], kh + 2);
                mma_f16(sa[2 * nbp],     qfh[ks], kl);
                mma_f16(sa[2 * nbp + 1], qfh[ks], kl + 2);
                mma_f16(sa[2 * nbp],     qfl[ks], kh);
                mma_f16(sa[2 * nbp + 1], qfl[ks], kh + 2);
            }
        }

        // ---- warp-private online softmax ----
        float rm0 = sa[0][0], rm1 = sa[0][2];
#pragma unroll
        for (int nb = 0; nb < 8; nb++) {
            rm0 = fmaxf(rm0, fmaxf(sa[nb][0], sa[nb][1]));
            rm1 = fmaxf(rm1, fmaxf(sa[nb][2], sa[nb][3]));
        }
        rm0 = fmaxf(rm0, __shfl_xor_sync(0xffffffffu, rm0, 1));
        rm0 = fmaxf(rm0, __shfl_xor_sync(0xffffffffu, rm0, 2));
        rm1 = fmaxf(rm1, __shfl_xor_sync(0xffffffffu, rm1, 1));
        rm1 = fmaxf(rm1, __shfl_xor_sync(0xffffffffu, rm1, 2));

        const float mn0 = fmaxf(mrow[0], rm0);
        const float mn1 = fmaxf(mrow[1], rm1);
        const float al0 = ex2f((mrow[0] - mn0) * LOG2E);
        const float al1 = ex2f((mrow[1] - mn1) * LOG2E);

        float rs0 = 0.f, rs1 = 0.f;
#pragma unroll
        for (int nb = 0; nb < 8; nb++) {
            sa[nb][0] = ex2f((sa[nb][0] - mn0) * LOG2E); rs0 += sa[nb][0];
            sa[nb][1] = ex2f((sa[nb][1] - mn0) * LOG2E); rs0 += sa[nb][1];
            sa[nb][2] = ex2f((sa[nb][2] - mn1) * LOG2E); rs1 += sa[nb][2];
            sa[nb][3] = ex2f((sa[nb][3] - mn1) * LOG2E); rs1 += sa[nb][3];
        }
        rs0 += __shfl_xor_sync(0xffffffffu, rs0, 1);
        rs0 += __shfl_xor_sync(0xffffffffu, rs0, 2);
        rs1 += __shfl_xor_sync(0xffffffffu, rs1, 1);
        rs1 += __shfl_xor_sync(0xffffffffu, rs1, 2);
        lrow[0] = lrow[0] * al0 + rs0;  mrow[0] = mn0;
        lrow[1] = lrow[1] * al1 + rs1;  mrow[1] = mn1;

#pragma unroll
        for (int nb = 0; nb < 16; nb++) {
            oa[nb][0] *= al0; oa[nb][1] *= al0;
            oa[nb][2] *= al1; oa[nb][3] *= al1;
        }

        // ---- O += P V (single fp16 term) ----
#pragma unroll
        for (int ks = 0; ks < 4; ks++) {
            uint32_t ph[4];
#pragma unroll
            for (int h = 0; h < 2; h++) {
                ph[2 * h]     = pack_h2(sa[2 * ks + h][0], sa[2 * ks + h][1]);
                ph[2 * h + 1] = pack_h2(sa[2 * ks + h][2], sa[2 * ks + h][3]);
            }
            const int chb = ks * 2 + (sub & 1);
#pragma unroll
            for (int nbp = 0; nbp < 8; nbp++) {
                uint32_t vh[4];
                int r = nbp * 16 + l7 + (sub >> 1) * 8;
                ldsm_x4(vh, vb + r * 128 + ((chb ^ (r & 7)) << 4));
                mma_f16(oa[2 * nbp],     ph, vh);
                mma_f16(oa[2 * nbp + 1], ph, vh + 2);
            }
        }
    }

    // ---- epilogue: write partial (A, m, l) to scratch ----
    const int r0 = qbase + m0 + (lane >> 2);
    const int r1 = r0 + 8;
    const int cb = (lane & 3) * 2;
    float* A0 = g_A + ((size_t)kvh * N_SEQ + r0) * HDIM;
    float* A1 = g_A + ((size_t)kvh * N_SEQ + r1) * HDIM;
#pragma unroll
    for (int nb = 0; nb < 16; nb++) {
        *reinterpret_cast<float2*>(A0 + nb * 8 + cb) = make_float2(oa[nb][0], oa[nb][1]);
        *reinterpret_cast<float2*>(A1 + nb * 8 + cb) = make_float2(oa[nb][2], oa[nb][3]);
    }
    if ((lane & 3) == 0) {
        g_M[kvh * N_SEQ + r0] = mrow[0];
        g_M[kvh * N_SEQ + r1] = mrow[1];
        g_L[kvh * N_SEQ + r0] = lrow[0];
        g_L[kvh * N_SEQ + r1] = lrow[1];
    }
}

// ---- merge the two KV halves ----
__global__ __launch_bounds__(256, 4)
void fa_merge_kernel(float* __restrict__ O) {
    int idx = blockIdx.x * blockDim.x + threadIdx.x;   // 8192*16
    int row = idx >> 4;
    int c8  = (idx & 15) * 8;
    float mA = g_M[row], mB = g_M[N_SEQ + row];
    float M = fmaxf(mA, mB);
    float wA = ex2f((mA - M) * LOG2E);
    float wB = ex2f((mB - M) * LOG2E);
    float l = wA * g_L[row] + wB * g_L[N_SEQ + row];
    float inv = 1.0f / l;
    const float* pA = g_A + (size_t)row * HDIM + c8;
    const float* pB = g_A + (size_t)(N_SEQ + row) * HDIM + c8;
    float* pO = O + (size_t)row * HDIM + c8;
#pragma unroll
    for (int h = 0; h < 2; h++) {
        float4 a = *reinterpret_cast<const float4*>(pA + 4 * h);
        float4 b = *reinterpret_cast<const float4*>(pB + 4 * h);
        float4 o;
        o.x = (a.x * wA + b.x * wB) * inv;
        o.y = (a.y * wA + b.y * wB) * inv;
        o.z = (a.z * wA + b.z * wB) * inv;
        o.w = (a.w * wA + b.w * wB) * inv;
        *reinterpret_cast<float4*>(pO + 4 * h) = o;
    }
}

extern "C" void kernel_launch(void* const* d_in, const int* in_sizes, int n_in,
                              void* d_out, int out_size) {
    const float* q = (const float*)d_in[0];
    const float* k = (const float*)d_in[1];
    const float* v = (const float*)d_in[2];
    float* o = (float*)d_out;
    (void)in_sizes; (void)n_in; (void)out_size;

    prep_k_kernel<<<(NTILES * 64 * 32) / 256, 256>>>(k);
    prep_v_kernel<<<(NTILES * 32 * 32) / 256, 256>>>(v);

    cudaFuncSetAttribute(fa_hmma_kernel,
                         cudaFuncAttributeMaxDynamicSharedMemorySize, SMEM_BYTES);
    fa_hmma_kernel<<<(N_SEQ / BM) * 2, THREADS, SMEM_BYTES>>>(q);
    fa_merge_kernel<<<(N_SEQ * 16) / 256, 256>>>(o);
}